// round 3
// baseline (speedup 1.0000x reference)
#include <cuda_runtime.h>
#include <cuda_bf16.h>
#include <math.h>
#include <stdint.h>

#define HIDDEN 3584
#define NQ 28
#define NKV 4
#define HD 128
#define SEQ 2048
#define BATCH 2
#define NREP (NQ / NKV)

// ---------------- scratch (static device arrays; no cudaMalloc) -------------
__device__ float g_tmp[BATCH * SEQ * HIDDEN];                 // GEMM out / context
__device__ float g_q[BATCH * NQ * SEQ * HD];                  // [B,Hq,S,D]
__device__ float g_k[BATCH * NKV * SEQ * HD];                 // [B,Hkv,S,D]
__device__ float g_v[BATCH * NKV * SEQ * HD];                 // [B,Hkv,S,D]
__device__ __nv_bfloat16 g_ah[BATCH * SEQ * HIDDEN];          // A hi
__device__ __nv_bfloat16 g_al[BATCH * SEQ * HIDDEN];          // A lo
__device__ __nv_bfloat16 g_wh[HIDDEN * HIDDEN];               // W hi (reused)
__device__ __nv_bfloat16 g_wl[HIDDEN * HIDDEN];               // W lo (reused)

// ---------------- fp32 -> (hi,lo) bf16 split quantizer ----------------------
__global__ void quant_kernel(const float* __restrict__ in,
                             __nv_bfloat16* __restrict__ hi,
                             __nv_bfloat16* __restrict__ lo, int n4)
{
    int i = blockIdx.x * blockDim.x + threadIdx.x;
    if (i >= n4) return;
    float4 v = ((const float4*)in)[i];
    __nv_bfloat16 h0 = __float2bfloat16(v.x);
    __nv_bfloat16 h1 = __float2bfloat16(v.y);
    __nv_bfloat16 h2 = __float2bfloat16(v.z);
    __nv_bfloat16 h3 = __float2bfloat16(v.w);
    __nv_bfloat16 l0 = __float2bfloat16(v.x - __bfloat162float(h0));
    __nv_bfloat16 l1 = __float2bfloat16(v.y - __bfloat162float(h1));
    __nv_bfloat16 l2 = __float2bfloat16(v.z - __bfloat162float(h2));
    __nv_bfloat16 l3 = __float2bfloat16(v.w - __bfloat162float(h3));
    __nv_bfloat162* hp = (__nv_bfloat162*)(hi + 4 * (size_t)i);
    __nv_bfloat162* lp = (__nv_bfloat162*)(lo + 4 * (size_t)i);
    hp[0] = __nv_bfloat162(h0, h1); hp[1] = __nv_bfloat162(h2, h3);
    lp[0] = __nv_bfloat162(l0, l1); lp[1] = __nv_bfloat162(l2, l3);
}

// ---------------- mma helpers -----------------------------------------------
__device__ __forceinline__ void ldsm4(uint32_t* r, uint32_t saddr)
{
    asm volatile("ldmatrix.sync.aligned.m8n8.x4.shared.b16 {%0,%1,%2,%3}, [%4];"
                 : "=r"(r[0]), "=r"(r[1]), "=r"(r[2]), "=r"(r[3]) : "r"(saddr));
}
__device__ __forceinline__ void mma_bf16(float* c, const uint32_t* a,
                                         uint32_t b0, uint32_t b1)
{
    asm volatile(
        "mma.sync.aligned.m16n8k16.row.col.f32.bf16.bf16.f32 "
        "{%0,%1,%2,%3}, {%4,%5,%6,%7}, {%8,%9}, {%0,%1,%2,%3};"
        : "+f"(c[0]), "+f"(c[1]), "+f"(c[2]), "+f"(c[3])
        : "r"(a[0]), "r"(a[1]), "r"(a[2]), "r"(a[3]), "r"(b0), "r"(b1));
}

// ---------------- split-bf16 tensor GEMM: C = A*W^T (+bias) -----------------
// A: [M,K] (hi/lo bf16), W: [N,K] (hi/lo bf16). M%128==0, N%128==0, K%32==0.
#define SA 40   // smem row stride in bf16 elems (32 data + 8 pad)

__global__ __launch_bounds__(256) void gemm_split(
    const __nv_bfloat16* __restrict__ Ah, const __nv_bfloat16* __restrict__ Al,
    const __nv_bfloat16* __restrict__ Wh, const __nv_bfloat16* __restrict__ Wl,
    const float* __restrict__ bias, float* __restrict__ C,
    int M, int N, int K)
{
    __shared__ __align__(16) __nv_bfloat16 sAh[128 * SA];
    __shared__ __align__(16) __nv_bfloat16 sAl[128 * SA];
    __shared__ __align__(16) __nv_bfloat16 sWh[128 * SA];
    __shared__ __align__(16) __nv_bfloat16 sWl[128 * SA];

    const int t    = threadIdx.x;
    const int lane = t & 31;
    const int wid  = t >> 5;
    const int wm   = (wid >> 2) * 64;   // warp m offset (0/64)
    const int wn   = (wid & 3) * 32;    // warp n offset (0..96)
    const int m0   = blockIdx.y * 128;
    const int n0   = blockIdx.x * 128;

    // copy mapping: chunk c -> row=c>>2, col=(c&3)*8 elems (16B)
    const int r1 = t >> 2, c1 = (t & 3) * 8;   // chunk t
    const int r2 = r1 + 64;                    // chunk t+256

    const __nv_bfloat16* pAh1 = Ah + (size_t)(m0 + r1) * K + c1;
    const __nv_bfloat16* pAh2 = Ah + (size_t)(m0 + r2) * K + c1;
    const __nv_bfloat16* pAl1 = Al + (size_t)(m0 + r1) * K + c1;
    const __nv_bfloat16* pAl2 = Al + (size_t)(m0 + r2) * K + c1;
    const __nv_bfloat16* pWh1 = Wh + (size_t)(n0 + r1) * K + c1;
    const __nv_bfloat16* pWh2 = Wh + (size_t)(n0 + r2) * K + c1;
    const __nv_bfloat16* pWl1 = Wl + (size_t)(n0 + r1) * K + c1;
    const __nv_bfloat16* pWl2 = Wl + (size_t)(n0 + r2) * K + c1;

    float acc[4][4][4];
#pragma unroll
    for (int i = 0; i < 4; i++)
#pragma unroll
        for (int j = 0; j < 4; j++)
#pragma unroll
            for (int e = 0; e < 4; e++) acc[i][j][e] = 0.f;

    uint4 st[8];
    st[0] = *(const uint4*)pAh1; st[1] = *(const uint4*)pAh2;
    st[2] = *(const uint4*)pAl1; st[3] = *(const uint4*)pAl2;
    st[4] = *(const uint4*)pWh1; st[5] = *(const uint4*)pWh2;
    st[6] = *(const uint4*)pWl1; st[7] = *(const uint4*)pWl2;

    const uint32_t bAh = (uint32_t)__cvta_generic_to_shared(sAh);
    const uint32_t bAl = (uint32_t)__cvta_generic_to_shared(sAl);
    const uint32_t bWh = (uint32_t)__cvta_generic_to_shared(sWh);
    const uint32_t bWl = (uint32_t)__cvta_generic_to_shared(sWl);

    for (int kt = 0; kt < K; kt += 32) {
        *(uint4*)&sAh[r1 * SA + c1] = st[0];
        *(uint4*)&sAh[r2 * SA + c1] = st[1];
        *(uint4*)&sAl[r1 * SA + c1] = st[2];
        *(uint4*)&sAl[r2 * SA + c1] = st[3];
        *(uint4*)&sWh[r1 * SA + c1] = st[4];
        *(uint4*)&sWh[r2 * SA + c1] = st[5];
        *(uint4*)&sWl[r1 * SA + c1] = st[6];
        *(uint4*)&sWl[r2 * SA + c1] = st[7];
        __syncthreads();

        if (kt + 32 < K) {
            st[0] = *(const uint4*)(pAh1 + kt + 32); st[1] = *(const uint4*)(pAh2 + kt + 32);
            st[2] = *(const uint4*)(pAl1 + kt + 32); st[3] = *(const uint4*)(pAl2 + kt + 32);
            st[4] = *(const uint4*)(pWh1 + kt + 32); st[5] = *(const uint4*)(pWh2 + kt + 32);
            st[6] = *(const uint4*)(pWl1 + kt + 32); st[7] = *(const uint4*)(pWl2 + kt + 32);
        }

#pragma unroll
        for (int kk = 0; kk < 32; kk += 16) {
            const int arow = (lane & 15);
            const int acol = kk + (lane >> 4) * 8;
            uint32_t ah[4][4], al[4][4], bh[2][4], bl[2][4];
#pragma unroll
            for (int mi = 0; mi < 4; mi++) {
                uint32_t off = ((wm + mi * 16 + arow) * SA + acol) * 2;
                ldsm4(ah[mi], bAh + off);
                ldsm4(al[mi], bAl + off);
            }
#pragma unroll
            for (int bi = 0; bi < 2; bi++) {
                uint32_t off = ((wn + bi * 16 + arow) * SA + acol) * 2;
                ldsm4(bh[bi], bWh + off);
                ldsm4(bl[bi], bWl + off);
            }
#pragma unroll
            for (int mi = 0; mi < 4; mi++)
#pragma unroll
                for (int bi = 0; bi < 2; bi++)
#pragma unroll
                    for (int h = 0; h < 2; h++) {
                        float* c = acc[mi][bi * 2 + h];
                        mma_bf16(c, ah[mi], bh[bi][h], bh[bi][2 + h]);
                        mma_bf16(c, ah[mi], bl[bi][h], bl[bi][2 + h]);
                        mma_bf16(c, al[mi], bh[bi][h], bh[bi][2 + h]);
                    }
        }
        __syncthreads();
    }

    // epilogue
#pragma unroll
    for (int mi = 0; mi < 4; mi++) {
        int row0 = m0 + wm + mi * 16 + (lane >> 2);
#pragma unroll
        for (int nj = 0; nj < 4; nj++) {
            int col0 = n0 + wn + nj * 8 + (lane & 3) * 2;
            float b0 = bias ? bias[col0] : 0.f;
            float b1 = bias ? bias[col0 + 1] : 0.f;
            float* c = acc[mi][nj];
            float2 v0 = make_float2(c[0] + b0, c[1] + b1);
            float2 v1 = make_float2(c[2] + b0, c[3] + b1);
            *(float2*)&C[(size_t)row0 * N + col0]       = v0;
            *(float2*)&C[(size_t)(row0 + 8) * N + col0] = v1;
        }
    }
}

// ---------------- robust position decode (int64 / int32 / float32) ----------
__device__ __forceinline__ float get_pos(const void* pos, int s)
{
    const int* p32 = (const int*)pos;
    if (p32[2] == 1 && p32[3] == 0) {                 // int64
        return (float)((const long long*)pos)[s];
    } else if (p32[1] == 1 && p32[2] == 2) {          // int32
        return (float)p32[s];
    } else {                                          // float32
        return ((const float*)pos)[s];
    }
}

// ---------------- RoPE + transpose:  [B,S,H,D] -> [B,H,S,D] -----------------
__global__ void rope_kernel(const float* __restrict__ in, float* __restrict__ out,
                            const void* __restrict__ pos, int H, int total)
{
    int idx = blockIdx.x * blockDim.x + threadIdx.x;
    if (idx >= total) return;          // total = B*H*S*64
    int per = idx;
    int d = per & 63;     per >>= 6;
    int s = per & (SEQ - 1); per /= SEQ;
    int h = per % H;
    int b = per / H;

    size_t ibase = (((size_t)b * SEQ + s) * H + h) * HD;
    float x1 = in[ibase + d];
    float x2 = in[ibase + d + 64];

    float inv = powf(1000000.0f, -(float)d / 64.0f);
    float ang = get_pos(pos, s) * inv;
    float sn, cs;
    sincosf(ang, &sn, &cs);

    size_t obase = (((size_t)b * H + h) * SEQ + s) * HD;
    out[obase + d]      = x1 * cs - x2 * sn;
    out[obase + d + 64] = x2 * cs + x1 * sn;
}

// ---------------- plain transpose for V: [B,S,H,D] -> [B,H,S,D] -------------
__global__ void vtrans_kernel(const float* __restrict__ in, float* __restrict__ out,
                              int total)
{
    int idx = blockIdx.x * blockDim.x + threadIdx.x;
    if (idx >= total) return;          // total = B*NKV*SEQ*HD
    int per = idx;
    int d = per & (HD - 1);  per >>= 7;
    int s = per & (SEQ - 1); per /= SEQ;
    int h = per % NKV;
    int b = per / NKV;
    out[idx] = in[(((size_t)b * SEQ + s) * NKV + h) * HD + d];
}

// ---------------- flash attention (fp32), output in [B,S,Hq*D] --------------
#define AQ 64
#define AK 32
#define QSCALE 0.08838834764831845f   // 1/sqrt(128)

__global__ __launch_bounds__(256, 2) void attn_kernel(
    const float* __restrict__ Qg, const float* __restrict__ Kg,
    const float* __restrict__ Vg, const float* __restrict__ maskg,
    float* __restrict__ Out)
{
    __shared__ float Ks[AK * HD];
    __shared__ float Vs[AK * HD];
    __shared__ float Ms[AQ * AK];

    const int t   = threadIdx.x;
    const int row = t >> 2;
    const int p   = t & 3;
    const int qt  = blockIdx.x;
    const int h   = blockIdx.y;
    const int b   = blockIdx.z;
    const int hkv = h / NREP;
    const int qr  = qt * AQ + row;

    const float* Qrow = Qg + (((size_t)(b * NQ + h) * SEQ) + qr) * HD + p * 32;
    float q[32];
#pragma unroll
    for (int i = 0; i < 32; i += 4) {
        float4 v4 = *(const float4*)(Qrow + i);
        q[i]     = v4.x * QSCALE;
        q[i + 1] = v4.y * QSCALE;
        q[i + 2] = v4.z * QSCALE;
        q[i + 3] = v4.w * QSCALE;
    }

    float o[32];
#pragma unroll
    for (int i = 0; i < 32; i++) o[i] = 0.f;
    float mcur = -INFINITY, l = 0.f;

    const float* Kbase = Kg + (size_t)(b * NKV + hkv) * SEQ * HD;
    const float* Vbase = Vg + (size_t)(b * NKV + hkv) * SEQ * HD;
    const float* Mbase = maskg + ((size_t)b * SEQ + (size_t)qt * AQ) * SEQ;

    for (int k0 = 0; k0 < SEQ; k0 += AK) {
        const float* ks = Kbase + (size_t)k0 * HD;
        const float* vs = Vbase + (size_t)k0 * HD;
#pragma unroll
        for (int i = 0; i < 4; i++) {
            int idx = (i * 256 + t) * 4;
            *(float4*)(Ks + idx) = *(const float4*)(ks + idx);
            *(float4*)(Vs + idx) = *(const float4*)(vs + idx);
        }
#pragma unroll
        for (int i = 0; i < 2; i++) {
            int idx = (i * 256 + t) * 4;
            int r = idx >> 5, c = idx & 31;
            *(float4*)(Ms + idx) = *(const float4*)(Mbase + (size_t)r * SEQ + k0 + c);
        }
        __syncthreads();

        float s[AK];
#pragma unroll
        for (int j = 0; j < AK; j++) {
            const float4* kr = (const float4*)(Ks + j * HD + p * 32);
            float acc = 0.f;
#pragma unroll
            for (int i4 = 0; i4 < 8; i4++) {
                float4 kv = kr[i4];
                acc += q[4 * i4]     * kv.x;
                acc += q[4 * i4 + 1] * kv.y;
                acc += q[4 * i4 + 2] * kv.z;
                acc += q[4 * i4 + 3] * kv.w;
            }
            s[j] = acc;
        }
#pragma unroll
        for (int j = 0; j < AK; j++) {
            s[j] += __shfl_xor_sync(0xffffffffu, s[j], 1);
            s[j] += __shfl_xor_sync(0xffffffffu, s[j], 2);
            s[j] += Ms[row * AK + j];
        }

        float mt = mcur;
#pragma unroll
        for (int j = 0; j < AK; j++) mt = fmaxf(mt, s[j]);
        float corr = __expf(mcur - mt);
        mcur = mt;
        l *= corr;
#pragma unroll
        for (int i = 0; i < 32; i++) o[i] *= corr;

#pragma unroll
        for (int j = 0; j < AK; j++) {
            float pj = __expf(s[j] - mcur);
            l += pj;
            const float4* vr = (const float4*)(Vs + j * HD + p * 32);
#pragma unroll
            for (int i4 = 0; i4 < 8; i4++) {
                float4 vv = vr[i4];
                o[4 * i4]     += pj * vv.x;
                o[4 * i4 + 1] += pj * vv.y;
                o[4 * i4 + 2] += pj * vv.z;
                o[4 * i4 + 3] += pj * vv.w;
            }
        }
        __syncthreads();
    }

    float inv = 1.f / l;
    float* orow = Out + ((size_t)b * SEQ + qr) * (NQ * HD) + h * HD + p * 32;
#pragma unroll
    for (int i = 0; i < 32; i += 4) {
        float4 v4;
        v4.x = o[i] * inv; v4.y = o[i + 1] * inv;
        v4.z = o[i + 2] * inv; v4.w = o[i + 3] * inv;
        *(float4*)(orow + i) = v4;
    }
}

// ---------------- launcher ---------------------------------------------------
static inline void quantize(const float* src, __nv_bfloat16* hi, __nv_bfloat16* lo,
                            size_t n)
{
    int n4 = (int)(n / 4);
    quant_kernel<<<(n4 + 255) / 256, 256>>>(src, hi, lo, n4);
}

extern "C" void kernel_launch(void* const* d_in, const int* in_sizes, int n_in,
                              void* d_out, int out_size)
{
    const float* X    = (const float*)d_in[0];
    const float* mask = (const float*)d_in[1];
    const void*  pos  = (const void*)d_in[2];
    const float* wq   = (const float*)d_in[3];
    const float* bq   = (const float*)d_in[4];
    const float* wk   = (const float*)d_in[5];
    const float* bk   = (const float*)d_in[6];
    const float* wv   = (const float*)d_in[7];
    const float* bv   = (const float*)d_in[8];
    const float* wo   = (const float*)d_in[9];
    float*       out  = (float*)d_out;

    float *tmp, *qb, *kb, *vb;
    __nv_bfloat16 *ah, *al, *wh, *wl;
    cudaGetSymbolAddress((void**)&tmp, g_tmp);
    cudaGetSymbolAddress((void**)&qb,  g_q);
    cudaGetSymbolAddress((void**)&kb,  g_k);
    cudaGetSymbolAddress((void**)&vb,  g_v);
    cudaGetSymbolAddress((void**)&ah,  g_ah);
    cudaGetSymbolAddress((void**)&al,  g_al);
    cudaGetSymbolAddress((void**)&wh,  g_wh);
    cudaGetSymbolAddress((void**)&wl,  g_wl);

    const int M = BATCH * SEQ;   // 4096

    quantize(X, ah, al, (size_t)M * HIDDEN);

    // Q projection + RoPE
    {
        quantize(wq, wh, wl, (size_t)(NQ * HD) * HIDDEN);
        dim3 grid((NQ * HD) / 128, M / 128);
        gemm_split<<<grid, 256>>>(ah, al, wh, wl, bq, tmp, M, NQ * HD, HIDDEN);
        int total = BATCH * NQ * SEQ * 64;
        rope_kernel<<<(total + 255) / 256, 256>>>(tmp, qb, pos, NQ, total);
    }
    // K projection + RoPE
    {
        quantize(wk, wh, wl, (size_t)(NKV * HD) * HIDDEN);
        dim3 grid((NKV * HD) / 128, M / 128);
        gemm_split<<<grid, 256>>>(ah, al, wh, wl, bk, tmp, M, NKV * HD, HIDDEN);
        int total = BATCH * NKV * SEQ * 64;
        rope_kernel<<<(total + 255) / 256, 256>>>(tmp, kb, pos, NKV, total);
    }
    // V projection + transpose
    {
        quantize(wv, wh, wl, (size_t)(NKV * HD) * HIDDEN);
        dim3 grid((NKV * HD) / 128, M / 128);
        gemm_split<<<grid, 256>>>(ah, al, wh, wl, bv, tmp, M, NKV * HD, HIDDEN);
        int total = BATCH * NKV * SEQ * HD;
        vtrans_kernel<<<(total + 255) / 256, 256>>>(tmp, vb, total);
    }
    // attention -> context in [B,S,Hq*D]
    {
        dim3 grid(SEQ / AQ, NQ, BATCH);
        attn_kernel<<<grid, 256>>>(qb, kb, vb, mask, tmp);
    }
    // output projection (no bias)
    {
        quantize(tmp, ah, al, (size_t)M * HIDDEN);
        quantize(wo, wh, wl, (size_t)HIDDEN * HIDDEN);
        dim3 grid(HIDDEN / 128, M / 128);
        gemm_split<<<grid, 256>>>(ah, al, wh, wl, nullptr, out, M, HIDDEN, HIDDEN);
    }
}

// round 4
// speedup vs baseline: 1.6525x; 1.6525x over previous
#include <cuda_runtime.h>
#include <cuda_bf16.h>
#include <math.h>
#include <stdint.h>

#define HIDDEN 3584
#define NQ 28
#define NKV 4
#define HD 128
#define SEQ 2048
#define BATCH 2
#define NREP (NQ / NKV)

// ---------------- scratch (static device arrays; no cudaMalloc) -------------
__device__ float g_tmp[BATCH * SEQ * HIDDEN];                 // GEMM out / context
__device__ float g_q[BATCH * NQ * SEQ * HD];                  // [B,Hq,S,D]
__device__ float g_k[BATCH * NKV * SEQ * HD];                 // [B,Hkv,S,D]
__device__ float g_v[BATCH * NKV * SEQ * HD];                 // [B,Hkv,S,D]
__device__ __nv_bfloat16 g_ah[BATCH * SEQ * HIDDEN];          // A hi
__device__ __nv_bfloat16 g_al[BATCH * SEQ * HIDDEN];          // A lo
__device__ __nv_bfloat16 g_wh[HIDDEN * HIDDEN];               // W hi (reused)
__device__ __nv_bfloat16 g_wl[HIDDEN * HIDDEN];               // W lo (reused)

// ---------------- fp32 -> (hi,lo) bf16 split quantizer ----------------------
__global__ void quant_kernel(const float* __restrict__ in,
                             __nv_bfloat16* __restrict__ hi,
                             __nv_bfloat16* __restrict__ lo, int n4)
{
    int i = blockIdx.x * blockDim.x + threadIdx.x;
    if (i >= n4) return;
    float4 v = ((const float4*)in)[i];
    __nv_bfloat16 h0 = __float2bfloat16(v.x);
    __nv_bfloat16 h1 = __float2bfloat16(v.y);
    __nv_bfloat16 h2 = __float2bfloat16(v.z);
    __nv_bfloat16 h3 = __float2bfloat16(v.w);
    __nv_bfloat16 l0 = __float2bfloat16(v.x - __bfloat162float(h0));
    __nv_bfloat16 l1 = __float2bfloat16(v.y - __bfloat162float(h1));
    __nv_bfloat16 l2 = __float2bfloat16(v.z - __bfloat162float(h2));
    __nv_bfloat16 l3 = __float2bfloat16(v.w - __bfloat162float(h3));
    __nv_bfloat162* hp = (__nv_bfloat162*)(hi + 4 * (size_t)i);
    __nv_bfloat162* lp = (__nv_bfloat162*)(lo + 4 * (size_t)i);
    hp[0] = __nv_bfloat162(h0, h1); hp[1] = __nv_bfloat162(h2, h3);
    lp[0] = __nv_bfloat162(l0, l1); lp[1] = __nv_bfloat162(l2, l3);
}

// ---------------- mma / cp.async helpers ------------------------------------
__device__ __forceinline__ void ldsm4(uint32_t* r, uint32_t saddr)
{
    asm volatile("ldmatrix.sync.aligned.m8n8.x4.shared.b16 {%0,%1,%2,%3}, [%4];"
                 : "=r"(r[0]), "=r"(r[1]), "=r"(r[2]), "=r"(r[3]) : "r"(saddr));
}
__device__ __forceinline__ void mma_bf16(float* c, const uint32_t* a,
                                         uint32_t b0, uint32_t b1)
{
    asm volatile(
        "mma.sync.aligned.m16n8k16.row.col.f32.bf16.bf16.f32 "
        "{%0,%1,%2,%3}, {%4,%5,%6,%7}, {%8,%9}, {%0,%1,%2,%3};"
        : "+f"(c[0]), "+f"(c[1]), "+f"(c[2]), "+f"(c[3])
        : "r"(a[0]), "r"(a[1]), "r"(a[2]), "r"(a[3]), "r"(b0), "r"(b1));
}
__device__ __forceinline__ void cp16(uint32_t dst, const void* src)
{
    asm volatile("cp.async.ca.shared.global [%0], [%1], 16;" :: "r"(dst), "l"(src));
}
#define CP_COMMIT() asm volatile("cp.async.commit_group;")
#define CP_WAIT0()  asm volatile("cp.async.wait_group 0;")

// ---------------- phase-GEMM: C = Ah*Wh^T + Ah*Wl^T + Al*Wh^T (+bias) -------
// A*: [M,K] bf16, W*: [N,K] bf16. M,N %128==0, K%32==0.
#define SA 40   // smem row stride in bf16 (32 data + 8 pad)

__global__ __launch_bounds__(256) void gemm_phase(
    const __nv_bfloat16* __restrict__ Ah, const __nv_bfloat16* __restrict__ Al,
    const __nv_bfloat16* __restrict__ Wh, const __nv_bfloat16* __restrict__ Wl,
    const float* __restrict__ bias, float* __restrict__ C,
    int M, int N, int K)
{
    __shared__ __align__(16) __nv_bfloat16 sA[2][128 * SA];
    __shared__ __align__(16) __nv_bfloat16 sW[2][128 * SA];

    const int t    = threadIdx.x;
    const int lane = t & 31;
    const int wid  = t >> 5;
    const int wm   = (wid >> 2) * 64;   // warp m offset (0/64)
    const int wn   = (wid & 3) * 32;    // warp n offset (0..96)
    const int m0   = blockIdx.y * 128;
    const int n0   = blockIdx.x * 128;

    const int r1 = t >> 2;              // 0..63
    const int r2 = r1 + 64;
    const int c1 = (t & 3) * 8;         // 0,8,16,24

    const int nk = K / 32;
    const int KT = 3 * nk;

    float acc[4][4][4];
#pragma unroll
    for (int i = 0; i < 4; i++)
#pragma unroll
        for (int j = 0; j < 4; j++)
#pragma unroll
            for (int e = 0; e < 4; e++) acc[i][j][e] = 0.f;

    const uint32_t smA[2] = {(uint32_t)__cvta_generic_to_shared(sA[0]),
                             (uint32_t)__cvta_generic_to_shared(sA[1])};
    const uint32_t smW[2] = {(uint32_t)__cvta_generic_to_shared(sW[0]),
                             (uint32_t)__cvta_generic_to_shared(sW[1])};

    // issue loads for one tile into buffer `buf`
    auto issue = [&](int tile, int buf) {
        int ph = tile / nk;
        int kk = (tile - ph * nk) * 32;
        const __nv_bfloat16* As = (ph < 2) ? Ah : Al;
        const __nv_bfloat16* Ws = (ph == 1) ? Wl : Wh;
        uint32_t dA = smA[buf], dW = smW[buf];
        cp16(dA + (r1 * SA + c1) * 2, As + (size_t)(m0 + r1) * K + kk + c1);
        cp16(dA + (r2 * SA + c1) * 2, As + (size_t)(m0 + r2) * K + kk + c1);
        cp16(dW + (r1 * SA + c1) * 2, Ws + (size_t)(n0 + r1) * K + kk + c1);
        cp16(dW + (r2 * SA + c1) * 2, Ws + (size_t)(n0 + r2) * K + kk + c1);
        CP_COMMIT();
    };

    issue(0, 0);

    for (int p = 0; p < KT; p++) {
        int cur = p & 1;
        CP_WAIT0();
        __syncthreads();
        if (p + 1 < KT) issue(p + 1, cur ^ 1);

        const uint32_t bA = smA[cur];
        const uint32_t bW = smW[cur];
#pragma unroll
        for (int kk = 0; kk < 32; kk += 16) {
            const int arow = (lane & 15);
            const int acol = kk + (lane >> 4) * 8;
            uint32_t a[4][4], bfr[2][4];
#pragma unroll
            for (int mi = 0; mi < 4; mi++)
                ldsm4(a[mi], bA + ((wm + mi * 16 + arow) * SA + acol) * 2);
#pragma unroll
            for (int bi = 0; bi < 2; bi++)
                ldsm4(bfr[bi], bW + ((wn + bi * 16 + arow) * SA + acol) * 2);
#pragma unroll
            for (int mi = 0; mi < 4; mi++)
#pragma unroll
                for (int bi = 0; bi < 2; bi++)
#pragma unroll
                    for (int h = 0; h < 2; h++)
                        mma_bf16(acc[mi][bi * 2 + h], a[mi],
                                 bfr[bi][h], bfr[bi][2 + h]);
        }
        __syncthreads();
    }

    // epilogue
#pragma unroll
    for (int mi = 0; mi < 4; mi++) {
        int row0 = m0 + wm + mi * 16 + (lane >> 2);
#pragma unroll
        for (int nj = 0; nj < 4; nj++) {
            int col0 = n0 + wn + nj * 8 + (lane & 3) * 2;
            float b0 = bias ? bias[col0] : 0.f;
            float b1 = bias ? bias[col0 + 1] : 0.f;
            float* c = acc[mi][nj];
            float2 v0 = make_float2(c[0] + b0, c[1] + b1);
            float2 v1 = make_float2(c[2] + b0, c[3] + b1);
            *(float2*)&C[(size_t)row0 * N + col0]       = v0;
            *(float2*)&C[(size_t)(row0 + 8) * N + col0] = v1;
        }
    }
}

// ---------------- robust position decode (int64 / int32 / float32) ----------
__device__ __forceinline__ float get_pos(const void* pos, int s)
{
    const int* p32 = (const int*)pos;
    if (p32[2] == 1 && p32[3] == 0) {                 // int64
        return (float)((const long long*)pos)[s];
    } else if (p32[1] == 1 && p32[2] == 2) {          // int32
        return (float)p32[s];
    } else {                                          // float32
        return ((const float*)pos)[s];
    }
}

// ---------------- RoPE + transpose:  [B,S,H,D] -> [B,H,S,D] -----------------
__global__ void rope_kernel(const float* __restrict__ in, float* __restrict__ out,
                            const void* __restrict__ pos, int H, int total)
{
    int idx = blockIdx.x * blockDim.x + threadIdx.x;
    if (idx >= total) return;          // total = B*H*S*64
    int per = idx;
    int d = per & 63;     per >>= 6;
    int s = per & (SEQ - 1); per /= SEQ;
    int h = per % H;
    int b = per / H;

    size_t ibase = (((size_t)b * SEQ + s) * H + h) * HD;
    float x1 = in[ibase + d];
    float x2 = in[ibase + d + 64];

    float inv = powf(1000000.0f, -(float)d / 64.0f);
    float ang = get_pos(pos, s) * inv;
    float sn, cs;
    sincosf(ang, &sn, &cs);

    size_t obase = (((size_t)b * H + h) * SEQ + s) * HD;
    out[obase + d]      = x1 * cs - x2 * sn;
    out[obase + d + 64] = x2 * cs + x1 * sn;
}

// ---------------- plain transpose for V: [B,S,H,D] -> [B,H,S,D] -------------
__global__ void vtrans_kernel(const float* __restrict__ in, float* __restrict__ out,
                              int total)
{
    int idx = blockIdx.x * blockDim.x + threadIdx.x;
    if (idx >= total) return;          // total = B*NKV*SEQ*HD
    int per = idx;
    int d = per & (HD - 1);  per >>= 7;
    int s = per & (SEQ - 1); per /= SEQ;
    int h = per % NKV;
    int b = per / NKV;
    out[idx] = in[(((size_t)b * SEQ + s) * NKV + h) * HD + d];
}

// ---------------- flash attention (fp32), output in [B,S,Hq*D] --------------
#define AQ 64
#define AK 32
#define QSCALE 0.08838834764831845f   // 1/sqrt(128)

__global__ __launch_bounds__(256, 2) void attn_kernel(
    const float* __restrict__ Qg, const float* __restrict__ Kg,
    const float* __restrict__ Vg, const float* __restrict__ maskg,
    float* __restrict__ Out)
{
    __shared__ float Ks[AK * HD];
    __shared__ float Vs[AK * HD];
    __shared__ float Ms[AQ * AK];

    const int t   = threadIdx.x;
    const int row = t >> 2;
    const int p   = t & 3;
    const int qt  = blockIdx.x;
    const int h   = blockIdx.y;
    const int b   = blockIdx.z;
    const int hkv = h / NREP;
    const int qr  = qt * AQ + row;

    const float* Qrow = Qg + (((size_t)(b * NQ + h) * SEQ) + qr) * HD + p * 32;
    float q[32];
#pragma unroll
    for (int i = 0; i < 32; i += 4) {
        float4 v4 = *(const float4*)(Qrow + i);
        q[i]     = v4.x * QSCALE;
        q[i + 1] = v4.y * QSCALE;
        q[i + 2] = v4.z * QSCALE;
        q[i + 3] = v4.w * QSCALE;
    }

    float o[32];
#pragma unroll
    for (int i = 0; i < 32; i++) o[i] = 0.f;
    float mcur = -INFINITY, l = 0.f;

    const float* Kbase = Kg + (size_t)(b * NKV + hkv) * SEQ * HD;
    const float* Vbase = Vg + (size_t)(b * NKV + hkv) * SEQ * HD;
    const float* Mbase = maskg + ((size_t)b * SEQ + (size_t)qt * AQ) * SEQ;

    for (int k0 = 0; k0 < SEQ; k0 += AK) {
        const float* ks = Kbase + (size_t)k0 * HD;
        const float* vs = Vbase + (size_t)k0 * HD;
#pragma unroll
        for (int i = 0; i < 4; i++) {
            int idx = (i * 256 + t) * 4;
            *(float4*)(Ks + idx) = *(const float4*)(ks + idx);
            *(float4*)(Vs + idx) = *(const float4*)(vs + idx);
        }
#pragma unroll
        for (int i = 0; i < 2; i++) {
            int idx = (i * 256 + t) * 4;
            int r = idx >> 5, c = idx & 31;
            *(float4*)(Ms + idx) = *(const float4*)(Mbase + (size_t)r * SEQ + k0 + c);
        }
        __syncthreads();

        float s[AK];
#pragma unroll
        for (int j = 0; j < AK; j++) {
            const float4* kr = (const float4*)(Ks + j * HD + p * 32);
            float acc = 0.f;
#pragma unroll
            for (int i4 = 0; i4 < 8; i4++) {
                float4 kv = kr[i4];
                acc += q[4 * i4]     * kv.x;
                acc += q[4 * i4 + 1] * kv.y;
                acc += q[4 * i4 + 2] * kv.z;
                acc += q[4 * i4 + 3] * kv.w;
            }
            s[j] = acc;
        }
#pragma unroll
        for (int j = 0; j < AK; j++) {
            s[j] += __shfl_xor_sync(0xffffffffu, s[j], 1);
            s[j] += __shfl_xor_sync(0xffffffffu, s[j], 2);
            s[j] += Ms[row * AK + j];
        }

        float mt = mcur;
#pragma unroll
        for (int j = 0; j < AK; j++) mt = fmaxf(mt, s[j]);
        float corr = __expf(mcur - mt);
        mcur = mt;
        l *= corr;
#pragma unroll
        for (int i = 0; i < 32; i++) o[i] *= corr;

#pragma unroll
        for (int j = 0; j < AK; j++) {
            float pj = __expf(s[j] - mcur);
            l += pj;
            const float4* vr = (const float4*)(Vs + j * HD + p * 32);
#pragma unroll
            for (int i4 = 0; i4 < 8; i4++) {
                float4 vv = vr[i4];
                o[4 * i4]     += pj * vv.x;
                o[4 * i4 + 1] += pj * vv.y;
                o[4 * i4 + 2] += pj * vv.z;
                o[4 * i4 + 3] += pj * vv.w;
            }
        }
        __syncthreads();
    }

    float inv = 1.f / l;
    float* orow = Out + ((size_t)b * SEQ + qr) * (NQ * HD) + h * HD + p * 32;
#pragma unroll
    for (int i = 0; i < 32; i += 4) {
        float4 v4;
        v4.x = o[i] * inv; v4.y = o[i + 1] * inv;
        v4.z = o[i + 2] * inv; v4.w = o[i + 3] * inv;
        *(float4*)(orow + i) = v4;
    }
}

// ---------------- launcher ---------------------------------------------------
static inline void quantize(const float* src, __nv_bfloat16* hi, __nv_bfloat16* lo,
                            size_t n)
{
    int n4 = (int)(n / 4);
    quant_kernel<<<(n4 + 255) / 256, 256>>>(src, hi, lo, n4);
}

extern "C" void kernel_launch(void* const* d_in, const int* in_sizes, int n_in,
                              void* d_out, int out_size)
{
    const float* X    = (const float*)d_in[0];
    const float* mask = (const float*)d_in[1];
    const void*  pos  = (const void*)d_in[2];
    const float* wq   = (const float*)d_in[3];
    const float* bq   = (const float*)d_in[4];
    const float* wk   = (const float*)d_in[5];
    const float* bk   = (const float*)d_in[6];
    const float* wv   = (const float*)d_in[7];
    const float* bv   = (const float*)d_in[8];
    const float* wo   = (const float*)d_in[9];
    float*       out  = (float*)d_out;

    float *tmp, *qb, *kb, *vb;
    __nv_bfloat16 *ah, *al, *wh, *wl;
    cudaGetSymbolAddress((void**)&tmp, g_tmp);
    cudaGetSymbolAddress((void**)&qb,  g_q);
    cudaGetSymbolAddress((void**)&kb,  g_k);
    cudaGetSymbolAddress((void**)&vb,  g_v);
    cudaGetSymbolAddress((void**)&ah,  g_ah);
    cudaGetSymbolAddress((void**)&al,  g_al);
    cudaGetSymbolAddress((void**)&wh,  g_wh);
    cudaGetSymbolAddress((void**)&wl,  g_wl);

    const int M = BATCH * SEQ;   // 4096

    quantize(X, ah, al, (size_t)M * HIDDEN);

    // Q projection + RoPE
    {
        quantize(wq, wh, wl, (size_t)(NQ * HD) * HIDDEN);
        dim3 grid((NQ * HD) / 128, M / 128);
        gemm_phase<<<grid, 256>>>(ah, al, wh, wl, bq, tmp, M, NQ * HD, HIDDEN);
        int total = BATCH * NQ * SEQ * 64;
        rope_kernel<<<(total + 255) / 256, 256>>>(tmp, qb, pos, NQ, total);
    }
    // K projection + RoPE
    {
        quantize(wk, wh, wl, (size_t)(NKV * HD) * HIDDEN);
        dim3 grid((NKV * HD) / 128, M / 128);
        gemm_phase<<<grid, 256>>>(ah, al, wh, wl, bk, tmp, M, NKV * HD, HIDDEN);
        int total = BATCH * NKV * SEQ * 64;
        rope_kernel<<<(total + 255) / 256, 256>>>(tmp, kb, pos, NKV, total);
    }
    // V projection + transpose
    {
        quantize(wv, wh, wl, (size_t)(NKV * HD) * HIDDEN);
        dim3 grid((NKV * HD) / 128, M / 128);
        gemm_phase<<<grid, 256>>>(ah, al, wh, wl, bv, tmp, M, NKV * HD, HIDDEN);
        int total = BATCH * NKV * SEQ * HD;
        vtrans_kernel<<<(total + 255) / 256, 256>>>(tmp, vb, total);
    }
    // attention -> context in [B,S,Hq*D]
    {
        dim3 grid(SEQ / AQ, NQ, BATCH);
        attn_kernel<<<grid, 256>>>(qb, kb, vb, mask, tmp);
    }
    // output projection (no bias)
    {
        quantize(tmp, ah, al, (size_t)M * HIDDEN);
        quantize(wo, wh, wl, (size_t)HIDDEN * HIDDEN);
        dim3 grid(HIDDEN / 128, M / 128);
        gemm_phase<<<grid, 256>>>(ah, al, wh, wl, nullptr, out, M, HIDDEN, HIDDEN);
    }
}

// round 5
// speedup vs baseline: 12.6332x; 7.6447x over previous
#include <cuda_runtime.h>
#include <cuda_bf16.h>
#include <math.h>
#include <stdint.h>

#define HIDDEN 3584
#define NQ 28
#define NKV 4
#define HD 128
#define SEQ 2048
#define BATCH 2
#define NREP (NQ / NKV)
#define QSCALE 0.08838834764831845f   // 1/sqrt(128)

typedef __nv_bfloat16 bf16;

// ---------------- scratch (static device arrays; no cudaMalloc) -------------
__device__ float g_tmp[BATCH * SEQ * HIDDEN];          // GEMM out / context
__device__ bf16 g_ah[BATCH * SEQ * HIDDEN];            // A hi (GEMM input)
__device__ bf16 g_al[BATCH * SEQ * HIDDEN];            // A lo
__device__ bf16 g_wh[HIDDEN * HIDDEN];                 // W hi (reused)
__device__ bf16 g_wl[HIDDEN * HIDDEN];                 // W lo
__device__ bf16 g_qh[BATCH * NQ * SEQ * HD];           // Q hi [B,Hq,S,D] (pre-scaled)
__device__ bf16 g_ql[BATCH * NQ * SEQ * HD];
__device__ bf16 g_kh[BATCH * NKV * SEQ * HD];          // K hi [B,Hkv,S,D]
__device__ bf16 g_kl[BATCH * NKV * SEQ * HD];
__device__ bf16 g_vh[BATCH * NKV * HD * SEQ];          // V hi [B,Hkv,D,S]  (transposed)
__device__ bf16 g_vl[BATCH * NKV * HD * SEQ];

// ---------------- fp32 -> (hi,lo) bf16 split quantizer ----------------------
__global__ void quant_kernel(const float* __restrict__ in,
                             bf16* __restrict__ hi, bf16* __restrict__ lo, int n4)
{
    int i = blockIdx.x * blockDim.x + threadIdx.x;
    if (i >= n4) return;
    float4 v = ((const float4*)in)[i];
    bf16 h0 = __float2bfloat16(v.x), h1 = __float2bfloat16(v.y);
    bf16 h2 = __float2bfloat16(v.z), h3 = __float2bfloat16(v.w);
    bf16 l0 = __float2bfloat16(v.x - __bfloat162float(h0));
    bf16 l1 = __float2bfloat16(v.y - __bfloat162float(h1));
    bf16 l2 = __float2bfloat16(v.z - __bfloat162float(h2));
    bf16 l3 = __float2bfloat16(v.w - __bfloat162float(h3));
    __nv_bfloat162* hp = (__nv_bfloat162*)(hi + 4 * (size_t)i);
    __nv_bfloat162* lp = (__nv_bfloat162*)(lo + 4 * (size_t)i);
    hp[0] = __nv_bfloat162(h0, h1); hp[1] = __nv_bfloat162(h2, h3);
    lp[0] = __nv_bfloat162(l0, l1); lp[1] = __nv_bfloat162(l2, l3);
}

// ---------------- mma / cp.async helpers ------------------------------------
__device__ __forceinline__ void ldsm4(uint32_t* r, uint32_t saddr)
{
    asm volatile("ldmatrix.sync.aligned.m8n8.x4.shared.b16 {%0,%1,%2,%3}, [%4];"
                 : "=r"(r[0]), "=r"(r[1]), "=r"(r[2]), "=r"(r[3]) : "r"(saddr));
}
__device__ __forceinline__ void mma_bf16(float* c, const uint32_t* a,
                                         uint32_t b0, uint32_t b1)
{
    asm volatile(
        "mma.sync.aligned.m16n8k16.row.col.f32.bf16.bf16.f32 "
        "{%0,%1,%2,%3}, {%4,%5,%6,%7}, {%8,%9}, {%0,%1,%2,%3};"
        : "+f"(c[0]), "+f"(c[1]), "+f"(c[2]), "+f"(c[3])
        : "r"(a[0]), "r"(a[1]), "r"(a[2]), "r"(a[3]), "r"(b0), "r"(b1));
}
__device__ __forceinline__ void cp16(uint32_t dst, const void* src)
{
    asm volatile("cp.async.ca.shared.global [%0], [%1], 16;" :: "r"(dst), "l"(src));
}
#define CP_COMMIT() asm volatile("cp.async.commit_group;")
#define CP_WAIT0()  asm volatile("cp.async.wait_group 0;")

__device__ __forceinline__ uint32_t pack_bf2(float a, float b)
{
    __nv_bfloat162 t(__float2bfloat16(a), __float2bfloat16(b));
    return *(uint32_t*)&t;
}
__device__ __forceinline__ float qmax4(float v)
{
    v = fmaxf(v, __shfl_xor_sync(0xffffffffu, v, 1));
    v = fmaxf(v, __shfl_xor_sync(0xffffffffu, v, 2));
    return v;
}
__device__ __forceinline__ float qsum4(float v)
{
    v += __shfl_xor_sync(0xffffffffu, v, 1);
    v += __shfl_xor_sync(0xffffffffu, v, 2);
    return v;
}

// ---------------- phase-GEMM: C = Ah*Wh^T + Ah*Wl^T + Al*Wh^T (+bias) -------
#define SA 40

__global__ __launch_bounds__(256) void gemm_phase(
    const bf16* __restrict__ Ah, const bf16* __restrict__ Al,
    const bf16* __restrict__ Wh, const bf16* __restrict__ Wl,
    const float* __restrict__ bias, float* __restrict__ C,
    int M, int N, int K)
{
    __shared__ __align__(16) bf16 sA[2][128 * SA];
    __shared__ __align__(16) bf16 sW[2][128 * SA];

    const int t    = threadIdx.x;
    const int lane = t & 31;
    const int wid  = t >> 5;
    const int wm   = (wid >> 2) * 64;
    const int wn   = (wid & 3) * 32;
    const int m0   = blockIdx.y * 128;
    const int n0   = blockIdx.x * 128;

    const int r1 = t >> 2;
    const int r2 = r1 + 64;
    const int c1 = (t & 3) * 8;

    const int nk = K / 32;
    const int KT = 3 * nk;

    float acc[4][4][4];
#pragma unroll
    for (int i = 0; i < 4; i++)
#pragma unroll
        for (int j = 0; j < 4; j++)
#pragma unroll
            for (int e = 0; e < 4; e++) acc[i][j][e] = 0.f;

    const uint32_t smA[2] = {(uint32_t)__cvta_generic_to_shared(sA[0]),
                             (uint32_t)__cvta_generic_to_shared(sA[1])};
    const uint32_t smW[2] = {(uint32_t)__cvta_generic_to_shared(sW[0]),
                             (uint32_t)__cvta_generic_to_shared(sW[1])};

    auto issue = [&](int tile, int buf) {
        int ph = tile / nk;
        int kk = (tile - ph * nk) * 32;
        const bf16* As = (ph < 2) ? Ah : Al;
        const bf16* Ws = (ph == 1) ? Wl : Wh;
        uint32_t dA = smA[buf], dW = smW[buf];
        cp16(dA + (r1 * SA + c1) * 2, As + (size_t)(m0 + r1) * K + kk + c1);
        cp16(dA + (r2 * SA + c1) * 2, As + (size_t)(m0 + r2) * K + kk + c1);
        cp16(dW + (r1 * SA + c1) * 2, Ws + (size_t)(n0 + r1) * K + kk + c1);
        cp16(dW + (r2 * SA + c1) * 2, Ws + (size_t)(n0 + r2) * K + kk + c1);
        CP_COMMIT();
    };

    issue(0, 0);

    for (int p = 0; p < KT; p++) {
        int cur = p & 1;
        CP_WAIT0();
        __syncthreads();
        if (p + 1 < KT) issue(p + 1, cur ^ 1);

        const uint32_t bA = smA[cur];
        const uint32_t bW = smW[cur];
#pragma unroll
        for (int kk = 0; kk < 32; kk += 16) {
            const int arow = (lane & 15);
            const int acol = kk + (lane >> 4) * 8;
            uint32_t a[4][4], bfr[2][4];
#pragma unroll
            for (int mi = 0; mi < 4; mi++)
                ldsm4(a[mi], bA + ((wm + mi * 16 + arow) * SA + acol) * 2);
#pragma unroll
            for (int bi = 0; bi < 2; bi++)
                ldsm4(bfr[bi], bW + ((wn + bi * 16 + arow) * SA + acol) * 2);
#pragma unroll
            for (int mi = 0; mi < 4; mi++)
#pragma unroll
                for (int bi = 0; bi < 2; bi++)
#pragma unroll
                    for (int h = 0; h < 2; h++)
                        mma_bf16(acc[mi][bi * 2 + h], a[mi],
                                 bfr[bi][h], bfr[bi][2 + h]);
        }
        __syncthreads();
    }

#pragma unroll
    for (int mi = 0; mi < 4; mi++) {
        int row0 = m0 + wm + mi * 16 + (lane >> 2);
#pragma unroll
        for (int nj = 0; nj < 4; nj++) {
            int col0 = n0 + wn + nj * 8 + (lane & 3) * 2;
            float b0 = bias ? bias[col0] : 0.f;
            float b1 = bias ? bias[col0 + 1] : 0.f;
            float* c = acc[mi][nj];
            float2 v0 = make_float2(c[0] + b0, c[1] + b1);
            float2 v1 = make_float2(c[2] + b0, c[3] + b1);
            *(float2*)&C[(size_t)row0 * N + col0]       = v0;
            *(float2*)&C[(size_t)(row0 + 8) * N + col0] = v1;
        }
    }
}

// ---------------- robust position decode (int64 / int32 / float32) ----------
__device__ __forceinline__ float get_pos(const void* pos, int s)
{
    const int* p32 = (const int*)pos;
    if (p32[2] == 1 && p32[3] == 0) {
        return (float)((const long long*)pos)[s];
    } else if (p32[1] == 1 && p32[2] == 2) {
        return (float)p32[s];
    } else {
        return ((const float*)pos)[s];
    }
}

// ------- RoPE + transpose + scale + hi/lo split:  [B,S,H,D] -> [B,H,S,D] ----
__global__ void rope_split(const float* __restrict__ in,
                           bf16* __restrict__ oh, bf16* __restrict__ ol,
                           const void* __restrict__ pos, int H, float scale,
                           int total)
{
    int idx = blockIdx.x * blockDim.x + threadIdx.x;
    if (idx >= total) return;          // total = B*H*S*64
    int per = idx;
    int d = per & 63;     per >>= 6;
    int s = per & (SEQ - 1); per /= SEQ;
    int h = per % H;
    int b = per / H;

    size_t ibase = (((size_t)b * SEQ + s) * H + h) * HD;
    float x1 = in[ibase + d];
    float x2 = in[ibase + d + 64];

    float inv = powf(1000000.0f, -(float)d / 64.0f);
    float ang = get_pos(pos, s) * inv;
    float sn, cs;
    sincosf(ang, &sn, &cs);

    float v0 = (x1 * cs - x2 * sn) * scale;
    float v1 = (x2 * cs + x1 * sn) * scale;

    size_t obase = (((size_t)b * H + h) * SEQ + s) * HD;
    bf16 h0 = __float2bfloat16(v0);
    bf16 h1 = __float2bfloat16(v1);
    oh[obase + d]      = h0;
    oh[obase + d + 64] = h1;
    ol[obase + d]      = __float2bfloat16(v0 - __bfloat162float(h0));
    ol[obase + d + 64] = __float2bfloat16(v1 - __bfloat162float(h1));
}

// ---- V transpose + split: [B,S,Hkv,D] -> [B,Hkv,D,S] (hi/lo bf16) ----------
__global__ void vtrans_split(const float* __restrict__ in,
                             bf16* __restrict__ oh, bf16* __restrict__ ol,
                             int total)
{
    int idx = blockIdx.x * blockDim.x + threadIdx.x;
    if (idx >= total) return;          // total = B*NKV*HD*SEQ
    int per = idx;
    int s = per & (SEQ - 1); per >>= 11;
    int d = per & (HD - 1);  per >>= 7;
    int h = per % NKV;
    int b = per / NKV;
    float v = in[(((size_t)b * SEQ + s) * NKV + h) * HD + d];
    bf16 hh = __float2bfloat16(v);
    oh[idx] = hh;
    ol[idx] = __float2bfloat16(v - __bfloat162float(hh));
}

// ---------------- mma flash attention ----------------------------------------
// CTA: 64 q-rows, 4 warps (m16 each); tiles of 64 keys; D=128.
#define AQW 64
#define KTS 64
#define KSTR 136    // K/Q smem row stride (bf16)
#define VSTR 72     // Vt smem row stride (bf16)
#define MSTR 72     // mask smem row stride (f32)

#define SM_KH 0
#define SM_KL (SM_KH + KTS * KSTR * 2)          // 17408
#define SM_VH (SM_KL + KTS * KSTR * 2)          // 34816
#define SM_VL (SM_VH + HD * VSTR * 2)           // 53248
#define SM_MS (SM_VL + HD * VSTR * 2)           // 71680
#define SM_TOTAL (SM_MS + AQW * MSTR * 4)       // 90112

__global__ __launch_bounds__(128) void attn_mma(
    const bf16* __restrict__ Qh, const bf16* __restrict__ Ql,
    const bf16* __restrict__ Kh, const bf16* __restrict__ Kl,
    const bf16* __restrict__ Vh, const bf16* __restrict__ Vl,
    const float* __restrict__ maskg, float* __restrict__ Out)
{
    extern __shared__ __align__(16) char smraw[];
    const uint32_t smb = (uint32_t)__cvta_generic_to_shared(smraw);

    const int t    = threadIdx.x;
    const int lane = t & 31;
    const int w    = t >> 5;          // 0..3
    const int q0   = blockIdx.x * AQW;
    const int h    = blockIdx.y;
    const int b    = blockIdx.z;
    const int hkv  = h / NREP;
    const int wm   = w * 16;

    const bf16* qh_b = Qh + (((size_t)(b * NQ + h) * SEQ) + q0) * HD;
    const bf16* ql_b = Ql + (((size_t)(b * NQ + h) * SEQ) + q0) * HD;
    const bf16* kh_b = Kh + (size_t)(b * NKV + hkv) * SEQ * HD;
    const bf16* kl_b = Kl + (size_t)(b * NKV + hkv) * SEQ * HD;
    const bf16* vh_b = Vh + (size_t)(b * NKV + hkv) * HD * SEQ;
    const bf16* vl_b = Vl + (size_t)(b * NKV + hkv) * HD * SEQ;
    const float* m_b = maskg + ((size_t)b * SEQ + q0) * SEQ;

    // ---- stage Q tile (hi->KH area, lo->KL area), then load fragments ------
    for (int c = t; c < 1024; c += 128) {
        int row = c >> 4, off = (c & 15) * 8;
        cp16(smb + SM_KH + (row * KSTR + off) * 2, qh_b + (size_t)row * HD + off);
        cp16(smb + SM_KL + (row * KSTR + off) * 2, ql_b + (size_t)row * HD + off);
    }
    CP_COMMIT(); CP_WAIT0();
    __syncthreads();

    uint32_t qfh[8][4], qfl[8][4];
    {
        const int arow = lane & 15;
#pragma unroll
        for (int ks = 0; ks < 8; ks++) {
            int acol = ks * 16 + (lane >> 4) * 8;
            ldsm4(qfh[ks], smb + SM_KH + ((wm + arow) * KSTR + acol) * 2);
            ldsm4(qfl[ks], smb + SM_KL + ((wm + arow) * KSTR + acol) * 2);
        }
    }
    __syncthreads();   // Q staging consumed; K tiles may overwrite

    float O[16][4];
#pragma unroll
    for (int j = 0; j < 16; j++)
#pragma unroll
        for (int e = 0; e < 4; e++) O[j][e] = 0.f;
    float mrow0 = -1e30f, mrow1 = -1e30f;
    float lrow0 = 0.f, lrow1 = 0.f;

    for (int k0 = 0; k0 < SEQ; k0 += KTS) {
        // ---- load K (hi/lo), Vt (hi/lo), mask tile ----
        for (int c = t; c < 1024; c += 128) {
            int row = c >> 4, off = (c & 15) * 8;
            const size_t g = (size_t)(k0 + row) * HD + off;
            cp16(smb + SM_KH + (row * KSTR + off) * 2, kh_b + g);
            cp16(smb + SM_KL + (row * KSTR + off) * 2, kl_b + g);
        }
        for (int c = t; c < 1024; c += 128) {
            int row = c >> 3, off = (c & 7) * 8;
            const size_t g = (size_t)row * SEQ + k0 + off;
            cp16(smb + SM_VH + (row * VSTR + off) * 2, vh_b + g);
            cp16(smb + SM_VL + (row * VSTR + off) * 2, vl_b + g);
        }
        for (int c = t; c < 1024; c += 128) {
            int row = c >> 4, off = (c & 15) * 4;
            cp16(smb + SM_MS + (row * MSTR + off) * 4,
                 m_b + (size_t)row * SEQ + k0 + off);
        }
        CP_COMMIT(); CP_WAIT0();
        __syncthreads();

        // ---- scores: S = Qh*Kh + Qh*Kl + Ql*Kh  (m16 x n64, k=128) ----
        float sc[8][4];
#pragma unroll
        for (int j = 0; j < 8; j++)
#pragma unroll
            for (int e = 0; e < 4; e++) sc[j][e] = 0.f;

        const int arow = lane & 15;
#pragma unroll
        for (int ks = 0; ks < 8; ks++) {
            int acol = ks * 16 + (lane >> 4) * 8;
            uint32_t bh[4][4], bl[4][4];
#pragma unroll
            for (int n = 0; n < 4; n++) {
                uint32_t off = ((n * 16 + arow) * KSTR + acol) * 2;
                ldsm4(bh[n], smb + SM_KH + off);
                ldsm4(bl[n], smb + SM_KL + off);
            }
#pragma unroll
            for (int n = 0; n < 4; n++)
#pragma unroll
                for (int hh = 0; hh < 2; hh++) {
                    float* c = sc[n * 2 + hh];
                    mma_bf16(c, qfh[ks], bh[n][hh], bh[n][2 + hh]);
                    mma_bf16(c, qfh[ks], bl[n][hh], bl[n][2 + hh]);
                    mma_bf16(c, qfl[ks], bh[n][hh], bh[n][2 + hh]);
                }
        }

        // ---- + mask, online softmax ----
        const int r0 = wm + (lane >> 2);
        const int cq = (lane & 3) * 2;
        float mx0 = -1e30f, mx1 = -1e30f;
#pragma unroll
        for (int j = 0; j < 8; j++) {
            float2 mk0 = *(float2*)&smraw[SM_MS + ((r0)     * MSTR + j * 8 + cq) * 4];
            float2 mk1 = *(float2*)&smraw[SM_MS + ((r0 + 8) * MSTR + j * 8 + cq) * 4];
            sc[j][0] += mk0.x; sc[j][1] += mk0.y;
            sc[j][2] += mk1.x; sc[j][3] += mk1.y;
            mx0 = fmaxf(mx0, fmaxf(sc[j][0], sc[j][1]));
            mx1 = fmaxf(mx1, fmaxf(sc[j][2], sc[j][3]));
        }
        mx0 = qmax4(mx0); mx1 = qmax4(mx1);
        float mn0 = fmaxf(mrow0, mx0), mn1 = fmaxf(mrow1, mx1);
        float cr0 = __expf(mrow0 - mn0), cr1 = __expf(mrow1 - mn1);
        mrow0 = mn0; mrow1 = mn1;
        lrow0 *= cr0; lrow1 *= cr1;
#pragma unroll
        for (int j = 0; j < 16; j++) {
            O[j][0] *= cr0; O[j][1] *= cr0;
            O[j][2] *= cr1; O[j][3] *= cr1;
        }

        uint32_t aph[4][4], apl[4][4];
#pragma unroll
        for (int j = 0; j < 8; j++) {
            float p0 = __expf(sc[j][0] - mn0);
            float p1 = __expf(sc[j][1] - mn0);
            float p2 = __expf(sc[j][2] - mn1);
            float p3 = __expf(sc[j][3] - mn1);
            lrow0 += p0 + p1; lrow1 += p2 + p3;
            bf16 h0 = __float2bfloat16(p0), h1 = __float2bfloat16(p1);
            bf16 h2 = __float2bfloat16(p2), h3 = __float2bfloat16(p3);
            int kk = j >> 1, hi = j & 1;     // frag slot
            __nv_bfloat162 ph01(h0, h1), ph23(h2, h3);
            aph[kk][hi * 2 + 0] = *(uint32_t*)&ph01;
            aph[kk][hi * 2 + 1] = *(uint32_t*)&ph23;
            apl[kk][hi * 2 + 0] = pack_bf2(p0 - __bfloat162float(h0),
                                           p1 - __bfloat162float(h1));
            apl[kk][hi * 2 + 1] = pack_bf2(p2 - __bfloat162float(h2),
                                           p3 - __bfloat162float(h3));
        }

        // ---- PV: O += Ph*Vh + Ph*Vl + Pl*Vh  (m16 x n128, k=64 keys) ----
#pragma unroll
        for (int kk = 0; kk < 4; kk++) {
            int acol = kk * 16 + (lane >> 4) * 8;
#pragma unroll
            for (int n = 0; n < 8; n++) {
                uint32_t off = ((n * 16 + arow) * VSTR + acol) * 2;
                uint32_t bvh[4], bvl[4];
                ldsm4(bvh, smb + SM_VH + off);
                ldsm4(bvl, smb + SM_VL + off);
#pragma unroll
                for (int hh = 0; hh < 2; hh++) {
                    float* c = O[n * 2 + hh];
                    mma_bf16(c, aph[kk], bvh[hh], bvh[2 + hh]);
                    mma_bf16(c, aph[kk], bvl[hh], bvl[2 + hh]);
                    mma_bf16(c, apl[kk], bvh[hh], bvh[2 + hh]);
                }
            }
        }
        __syncthreads();   // tile consumed
    }

    // ---- finalize: O /= l, write context [B,S,NQ*D] ----
    float lt0 = qsum4(lrow0), lt1 = qsum4(lrow1);
    float inv0 = 1.f / lt0, inv1 = 1.f / lt1;

    const int r0 = q0 + wm + (lane >> 2);
    const int cq = (lane & 3) * 2;
    float* o_b = Out + ((size_t)b * SEQ) * (NQ * HD) + h * HD;
#pragma unroll
    for (int j = 0; j < 16; j++) {
        int col = j * 8 + cq;
        *(float2*)&o_b[(size_t)r0 * (NQ * HD) + col] =
            make_float2(O[j][0] * inv0, O[j][1] * inv0);
        *(float2*)&o_b[(size_t)(r0 + 8) * (NQ * HD) + col] =
            make_float2(O[j][2] * inv1, O[j][3] * inv1);
    }
}

// ---------------- launcher ----------------------------------------------------
static inline void quantize(const float* src, bf16* hi, bf16* lo, size_t n)
{
    int n4 = (int)(n / 4);
    quant_kernel<<<(n4 + 255) / 256, 256>>>(src, hi, lo, n4);
}

extern "C" void kernel_launch(void* const* d_in, const int* in_sizes, int n_in,
                              void* d_out, int out_size)
{
    const float* X    = (const float*)d_in[0];
    const float* mask = (const float*)d_in[1];
    const void*  pos  = (const void*)d_in[2];
    const float* wq   = (const float*)d_in[3];
    const float* bq   = (const float*)d_in[4];
    const float* wk   = (const float*)d_in[5];
    const float* bk   = (const float*)d_in[6];
    const float* wv   = (const float*)d_in[7];
    const float* bv   = (const float*)d_in[8];
    const float* wo   = (const float*)d_in[9];
    float*       out  = (float*)d_out;

    float *tmp;
    bf16 *ah, *al, *wh, *wl, *qh, *ql, *kh, *kl, *vh, *vl;
    cudaGetSymbolAddress((void**)&tmp, g_tmp);
    cudaGetSymbolAddress((void**)&ah,  g_ah);
    cudaGetSymbolAddress((void**)&al,  g_al);
    cudaGetSymbolAddress((void**)&wh,  g_wh);
    cudaGetSymbolAddress((void**)&wl,  g_wl);
    cudaGetSymbolAddress((void**)&qh,  g_qh);
    cudaGetSymbolAddress((void**)&ql,  g_ql);
    cudaGetSymbolAddress((void**)&kh,  g_kh);
    cudaGetSymbolAddress((void**)&kl,  g_kl);
    cudaGetSymbolAddress((void**)&vh,  g_vh);
    cudaGetSymbolAddress((void**)&vl,  g_vl);

    cudaFuncSetAttribute(attn_mma, cudaFuncAttributeMaxDynamicSharedMemorySize,
                         SM_TOTAL);

    const int M = BATCH * SEQ;   // 4096

    quantize(X, ah, al, (size_t)M * HIDDEN);

    // Q projection + RoPE (scaled) + split
    {
        quantize(wq, wh, wl, (size_t)(NQ * HD) * HIDDEN);
        dim3 grid((NQ * HD) / 128, M / 128);
        gemm_phase<<<grid, 256>>>(ah, al, wh, wl, bq, tmp, M, NQ * HD, HIDDEN);
        int total = BATCH * NQ * SEQ * 64;
        rope_split<<<(total + 255) / 256, 256>>>(tmp, qh, ql, pos, NQ, QSCALE, total);
    }
    // K projection + RoPE + split
    {
        quantize(wk, wh, wl, (size_t)(NKV * HD) * HIDDEN);
        dim3 grid((NKV * HD) / 128, M / 128);
        gemm_phase<<<grid, 256>>>(ah, al, wh, wl, bk, tmp, M, NKV * HD, HIDDEN);
        int total = BATCH * NKV * SEQ * 64;
        rope_split<<<(total + 255) / 256, 256>>>(tmp, kh, kl, pos, NKV, 1.0f, total);
    }
    // V projection + transpose + split
    {
        quantize(wv, wh, wl, (size_t)(NKV * HD) * HIDDEN);
        dim3 grid((NKV * HD) / 128, M / 128);
        gemm_phase<<<grid, 256>>>(ah, al, wh, wl, bv, tmp, M, NKV * HD, HIDDEN);
        int total = BATCH * NKV * HD * SEQ;
        vtrans_split<<<(total + 255) / 256, 256>>>(tmp, vh, vl, total);
    }
    // attention -> context in [B,S,Hq*D]
    {
        dim3 grid(SEQ / AQW, NQ, BATCH);
        attn_mma<<<grid, 128, SM_TOTAL>>>(qh, ql, kh, kl, vh, vl, mask, tmp);
    }
    // output projection (no bias)
    {
        quantize(tmp, ah, al, (size_t)M * HIDDEN);
        quantize(wo, wh, wl, (size_t)HIDDEN * HIDDEN);
        dim3 grid(HIDDEN / 128, M / 128);
        gemm_phase<<<grid, 256>>>(ah, al, wh, wl, nullptr, out, M, HIDDEN, HIDDEN);
    }
}

// round 7
// speedup vs baseline: 31.0138x; 2.4549x over previous
#include <cuda_runtime.h>
#include <cuda_bf16.h>
#include <cuda_fp16.h>
#include <math.h>
#include <stdint.h>

#define HIDDEN 3584
#define NQ 28
#define NKV 4
#define HD 128
#define SEQ 2048
#define BATCH 2
#define NREP (NQ / NKV)
#define QSCALE 0.08838834764831845f   // 1/sqrt(128)

// ---------------- scratch (static device arrays; no cudaMalloc) -------------
__device__ float g_tmp[BATCH * SEQ * HIDDEN];          // GEMM out / context
__device__ __half g_a[BATCH * SEQ * HIDDEN];           // GEMM A (fp16)
__device__ __half g_w[HIDDEN * HIDDEN];                // GEMM W (fp16, reused)
__device__ __half g_q[BATCH * NQ * SEQ * HD];          // Q [B,Hq,S,D] (pre-scaled)
__device__ __half g_k[BATCH * NKV * SEQ * HD];         // K [B,Hkv,S,D]
__device__ __half g_v[BATCH * NKV * HD * SEQ];         // V [B,Hkv,D,S] (transposed)

// ---------------- fp32 -> fp16 quantizer ------------------------------------
__global__ void quant_kernel(const float* __restrict__ in,
                             __half* __restrict__ out, int n4)
{
    int i = blockIdx.x * blockDim.x + threadIdx.x;
    if (i >= n4) return;
    float4 v = ((const float4*)in)[i];
    __half2* op = (__half2*)(out + 4 * (size_t)i);
    op[0] = __floats2half2_rn(v.x, v.y);
    op[1] = __floats2half2_rn(v.z, v.w);
}

// ---------------- mma / cp.async helpers ------------------------------------
__device__ __forceinline__ void ldsm4(uint32_t* r, uint32_t saddr)
{
    asm volatile("ldmatrix.sync.aligned.m8n8.x4.shared.b16 {%0,%1,%2,%3}, [%4];"
                 : "=r"(r[0]), "=r"(r[1]), "=r"(r[2]), "=r"(r[3]) : "r"(saddr));
}
__device__ __forceinline__ void mma_fp16(float* c, const uint32_t* a,
                                         uint32_t b0, uint32_t b1)
{
    asm volatile(
        "mma.sync.aligned.m16n8k16.row.col.f32.f16.f16.f32 "
        "{%0,%1,%2,%3}, {%4,%5,%6,%7}, {%8,%9}, {%0,%1,%2,%3};"
        : "+f"(c[0]), "+f"(c[1]), "+f"(c[2]), "+f"(c[3])
        : "r"(a[0]), "r"(a[1]), "r"(a[2]), "r"(a[3]), "r"(b0), "r"(b1));
}
__device__ __forceinline__ void cp16(uint32_t dst, const void* src)
{
    asm volatile("cp.async.ca.shared.global [%0], [%1], 16;" :: "r"(dst), "l"(src));
}
#define CP_COMMIT() asm volatile("cp.async.commit_group;")
#define CP_WAIT0()  asm volatile("cp.async.wait_group 0;")

__device__ __forceinline__ float qmax4(float v)
{
    v = fmaxf(v, __shfl_xor_sync(0xffffffffu, v, 1));
    v = fmaxf(v, __shfl_xor_sync(0xffffffffu, v, 2));
    return v;
}
__device__ __forceinline__ float qsum4(float v)
{
    v += __shfl_xor_sync(0xffffffffu, v, 1);
    v += __shfl_xor_sync(0xffffffffu, v, 2);
    return v;
}

// ---------------- fp16 tensor GEMM: C = A*W^T (+bias) -----------------------
// A: [M,K] fp16, W: [N,K] fp16. M,N %128==0, K%32==0.
#define SA 40

__global__ __launch_bounds__(256) void gemm_fp16(
    const __half* __restrict__ A, const __half* __restrict__ W,
    const float* __restrict__ bias, float* __restrict__ C,
    int M, int N, int K)
{
    __shared__ __align__(16) __half sA[2][128 * SA];
    __shared__ __align__(16) __half sW[2][128 * SA];

    const int t    = threadIdx.x;
    const int lane = t & 31;
    const int wid  = t >> 5;
    const int wm   = (wid >> 2) * 64;
    const int wn   = (wid & 3) * 32;
    const int m0   = blockIdx.y * 128;
    const int n0   = blockIdx.x * 128;

    const int r1 = t >> 2;
    const int r2 = r1 + 64;
    const int c1 = (t & 3) * 8;

    const int nk = K / 32;

    float acc[4][4][4];
#pragma unroll
    for (int i = 0; i < 4; i++)
#pragma unroll
        for (int j = 0; j < 4; j++)
#pragma unroll
            for (int e = 0; e < 4; e++) acc[i][j][e] = 0.f;

    const uint32_t smA[2] = {(uint32_t)__cvta_generic_to_shared(sA[0]),
                             (uint32_t)__cvta_generic_to_shared(sA[1])};
    const uint32_t smW[2] = {(uint32_t)__cvta_generic_to_shared(sW[0]),
                             (uint32_t)__cvta_generic_to_shared(sW[1])};

    auto issue = [&](int tile, int buf) {
        int kk = tile * 32;
        uint32_t dA = smA[buf], dW = smW[buf];
        cp16(dA + (r1 * SA + c1) * 2, A + (size_t)(m0 + r1) * K + kk + c1);
        cp16(dA + (r2 * SA + c1) * 2, A + (size_t)(m0 + r2) * K + kk + c1);
        cp16(dW + (r1 * SA + c1) * 2, W + (size_t)(n0 + r1) * K + kk + c1);
        cp16(dW + (r2 * SA + c1) * 2, W + (size_t)(n0 + r2) * K + kk + c1);
        CP_COMMIT();
    };

    issue(0, 0);

    for (int p = 0; p < nk; p++) {
        int cur = p & 1;
        CP_WAIT0();
        __syncthreads();
        if (p + 1 < nk) issue(p + 1, cur ^ 1);

        const uint32_t bA = smA[cur];
        const uint32_t bW = smW[cur];
#pragma unroll
        for (int kk = 0; kk < 32; kk += 16) {
            const int arow = (lane & 15);
            const int acol = kk + (lane >> 4) * 8;
            uint32_t a[4][4], bfr[2][4];
#pragma unroll
            for (int mi = 0; mi < 4; mi++)
                ldsm4(a[mi], bA + ((wm + mi * 16 + arow) * SA + acol) * 2);
#pragma unroll
            for (int bi = 0; bi < 2; bi++)
                ldsm4(bfr[bi], bW + ((wn + bi * 16 + arow) * SA + acol) * 2);
#pragma unroll
            for (int mi = 0; mi < 4; mi++)
#pragma unroll
                for (int bi = 0; bi < 2; bi++)
#pragma unroll
                    for (int h = 0; h < 2; h++)
                        mma_fp16(acc[mi][bi * 2 + h], a[mi],
                                 bfr[bi][h], bfr[bi][2 + h]);
        }
        __syncthreads();
    }

#pragma unroll
    for (int mi = 0; mi < 4; mi++) {
        int row0 = m0 + wm + mi * 16 + (lane >> 2);
#pragma unroll
        for (int nj = 0; nj < 4; nj++) {
            int col0 = n0 + wn + nj * 8 + (lane & 3) * 2;
            float b0 = bias ? bias[col0] : 0.f;
            float b1 = bias ? bias[col0 + 1] : 0.f;
            float* c = acc[mi][nj];
            float2 v0 = make_float2(c[0] + b0, c[1] + b1);
            float2 v1 = make_float2(c[2] + b0, c[3] + b1);
            *(float2*)&C[(size_t)row0 * N + col0]       = v0;
            *(float2*)&C[(size_t)(row0 + 8) * N + col0] = v1;
        }
    }
}

// ---------------- robust position decode (int64 / int32 / float32) ----------
__device__ __forceinline__ float get_pos(const void* pos, int s)
{
    const int* p32 = (const int*)pos;
    if (p32[2] == 1 && p32[3] == 0) {
        return (float)((const long long*)pos)[s];
    } else if (p32[1] == 1 && p32[2] == 2) {
        return (float)p32[s];
    } else {
        return ((const float*)pos)[s];
    }
}

// ------- RoPE + transpose + scale -> fp16:  [B,S,H,D] -> [B,H,S,D] ----------
__global__ void rope_half(const float* __restrict__ in, __half* __restrict__ out,
                          const void* __restrict__ pos, int H, float scale,
                          int total)
{
    int idx = blockIdx.x * blockDim.x + threadIdx.x;
    if (idx >= total) return;          // total = B*H*S*64
    int per = idx;
    int d = per & 63;     per >>= 6;
    int s = per & (SEQ - 1); per /= SEQ;
    int h = per % H;
    int b = per / H;

    size_t ibase = (((size_t)b * SEQ + s) * H + h) * HD;
    float x1 = in[ibase + d];
    float x2 = in[ibase + d + 64];

    float inv = powf(1000000.0f, -(float)d / 64.0f);
    float ang = get_pos(pos, s) * inv;
    float sn, cs;
    sincosf(ang, &sn, &cs);

    size_t obase = (((size_t)b * H + h) * SEQ + s) * HD;
    out[obase + d]      = __float2half((x1 * cs - x2 * sn) * scale);
    out[obase + d + 64] = __float2half((x2 * cs + x1 * sn) * scale);
}

// ---- V transpose -> fp16: [B,S,Hkv,D] -> [B,Hkv,D,S] -----------------------
__global__ void vtrans_half(const float* __restrict__ in, __half* __restrict__ out,
                            int total)
{
    int idx = blockIdx.x * blockDim.x + threadIdx.x;
    if (idx >= total) return;          // total = B*NKV*HD*SEQ
    int per = idx;
    int s = per & (SEQ - 1); per >>= 11;
    int d = per & (HD - 1);  per >>= 7;
    int h = per % NKV;
    int b = per / NKV;
    out[idx] = __float2half(in[(((size_t)b * SEQ + s) * NKV + h) * HD + d]);
}

// ---------------- mma flash attention (fp16) ---------------------------------
// CTA: 64 q-rows, 4 warps (m16 each); tiles of 64 keys; D=128.
#define AQW 64
#define KTS 64
#define KSTR 136    // K/Q smem row stride (fp16)
#define VSTR 72     // Vt smem row stride (fp16)
#define MSTR 72     // mask smem row stride (f32)

#define SM_K  0
#define SM_V  (SM_K + KTS * KSTR * 2)           // 17408
#define SM_MS (SM_V + HD * VSTR * 2)            // 35840
#define SM_TOTAL (SM_MS + AQW * MSTR * 4)       // 54272

__global__ __launch_bounds__(128) void attn_mma(
    const __half* __restrict__ Qg, const __half* __restrict__ Kg,
    const __half* __restrict__ Vg, const float* __restrict__ maskg,
    float* __restrict__ Out)
{
    extern __shared__ __align__(16) char smraw[];
    const uint32_t smb = (uint32_t)__cvta_generic_to_shared(smraw);

    const int t    = threadIdx.x;
    const int lane = t & 31;
    const int w    = t >> 5;
    const int q0   = blockIdx.x * AQW;
    const int h    = blockIdx.y;
    const int b    = blockIdx.z;
    const int hkv  = h / NREP;
    const int wm   = w * 16;

    const __half* q_b = Qg + (((size_t)(b * NQ + h) * SEQ) + q0) * HD;
    const __half* k_b = Kg + (size_t)(b * NKV + hkv) * SEQ * HD;
    const __half* v_b = Vg + (size_t)(b * NKV + hkv) * HD * SEQ;
    const float*  m_b = maskg + ((size_t)b * SEQ + q0) * SEQ;

    // ---- stage Q tile in K area, load fragments ----
    for (int c = t; c < 1024; c += 128) {
        int row = c >> 4, off = (c & 15) * 8;
        cp16(smb + SM_K + (row * KSTR + off) * 2, q_b + (size_t)row * HD + off);
    }
    CP_COMMIT(); CP_WAIT0();
    __syncthreads();

    uint32_t qf[8][4];
    {
        const int arow = lane & 15;
#pragma unroll
        for (int ks = 0; ks < 8; ks++) {
            int acol = ks * 16 + (lane >> 4) * 8;
            ldsm4(qf[ks], smb + SM_K + ((wm + arow) * KSTR + acol) * 2);
        }
    }
    __syncthreads();

    float O[16][4];
#pragma unroll
    for (int j = 0; j < 16; j++)
#pragma unroll
        for (int e = 0; e < 4; e++) O[j][e] = 0.f;
    float mrow0 = -1e30f, mrow1 = -1e30f;
    float lrow0 = 0.f, lrow1 = 0.f;

    for (int k0 = 0; k0 < SEQ; k0 += KTS) {
        // ---- load K, Vt, mask tile ----
        for (int c = t; c < 1024; c += 128) {
            int row = c >> 4, off = (c & 15) * 8;
            cp16(smb + SM_K + (row * KSTR + off) * 2,
                 k_b + (size_t)(k0 + row) * HD + off);
        }
        for (int c = t; c < 1024; c += 128) {
            int row = c >> 3, off = (c & 7) * 8;
            cp16(smb + SM_V + (row * VSTR + off) * 2,
                 v_b + (size_t)row * SEQ + k0 + off);
        }
        for (int c = t; c < 1024; c += 128) {
            int row = c >> 4, off = (c & 15) * 4;
            cp16(smb + SM_MS + (row * MSTR + off) * 4,
                 m_b + (size_t)row * SEQ + k0 + off);
        }
        CP_COMMIT(); CP_WAIT0();
        __syncthreads();

        // ---- scores: S = Q*K^T  (m16 x n64, k=128) ----
        float sc[8][4];
#pragma unroll
        for (int j = 0; j < 8; j++)
#pragma unroll
            for (int e = 0; e < 4; e++) sc[j][e] = 0.f;

        const int arow = lane & 15;
#pragma unroll
        for (int ks = 0; ks < 8; ks++) {
            int acol = ks * 16 + (lane >> 4) * 8;
#pragma unroll
            for (int n = 0; n < 4; n++) {
                uint32_t bk[4];
                ldsm4(bk, smb + SM_K + ((n * 16 + arow) * KSTR + acol) * 2);
#pragma unroll
                for (int hh = 0; hh < 2; hh++)
                    mma_fp16(sc[n * 2 + hh], qf[ks], bk[hh], bk[2 + hh]);
            }
        }

        // ---- + mask, online softmax ----
        const int r0 = wm + (lane >> 2);
        const int cq = (lane & 3) * 2;
        float mx0 = -1e30f, mx1 = -1e30f;
#pragma unroll
        for (int j = 0; j < 8; j++) {
            float2 mk0 = *(float2*)&smraw[SM_MS + ((r0)     * MSTR + j * 8 + cq) * 4];
            float2 mk1 = *(float2*)&smraw[SM_MS + ((r0 + 8) * MSTR + j * 8 + cq) * 4];
            sc[j][0] += mk0.x; sc[j][1] += mk0.y;
            sc[j][2] += mk1.x; sc[j][3] += mk1.y;
            mx0 = fmaxf(mx0, fmaxf(sc[j][0], sc[j][1]));
            mx1 = fmaxf(mx1, fmaxf(sc[j][2], sc[j][3]));
        }
        mx0 = qmax4(mx0); mx1 = qmax4(mx1);
        float mn0 = fmaxf(mrow0, mx0), mn1 = fmaxf(mrow1, mx1);
        float cr0 = __expf(mrow0 - mn0), cr1 = __expf(mrow1 - mn1);
        mrow0 = mn0; mrow1 = mn1;
        lrow0 *= cr0; lrow1 *= cr1;
#pragma unroll
        for (int j = 0; j < 16; j++) {
            O[j][0] *= cr0; O[j][1] *= cr0;
            O[j][2] *= cr1; O[j][3] *= cr1;
        }

        uint32_t ap[4][4];
#pragma unroll
        for (int j = 0; j < 8; j++) {
            float p0 = __expf(sc[j][0] - mn0);
            float p1 = __expf(sc[j][1] - mn0);
            float p2 = __expf(sc[j][2] - mn1);
            float p3 = __expf(sc[j][3] - mn1);
            lrow0 += p0 + p1; lrow1 += p2 + p3;
            int kk = j >> 1, hi = j & 1;
            __half2 ph01 = __floats2half2_rn(p0, p1);
            __half2 ph23 = __floats2half2_rn(p2, p3);
            ap[kk][hi * 2 + 0] = *(uint32_t*)&ph01;
            ap[kk][hi * 2 + 1] = *(uint32_t*)&ph23;
        }

        // ---- PV: O += P*V^T  (m16 x n128, k=64 keys) ----
#pragma unroll
        for (int kk = 0; kk < 4; kk++) {
            int acol = kk * 16 + (lane >> 4) * 8;
#pragma unroll
            for (int n = 0; n < 8; n++) {
                uint32_t bv[4];
                ldsm4(bv, smb + SM_V + ((n * 16 + arow) * VSTR + acol) * 2);
#pragma unroll
                for (int hh = 0; hh < 2; hh++)
                    mma_fp16(O[n * 2 + hh], ap[kk], bv[hh], bv[2 + hh]);
            }
        }
        __syncthreads();
    }

    // ---- finalize: O /= l, write context [B,S,NQ*D] ----
    float lt0 = qsum4(lrow0), lt1 = qsum4(lrow1);
    float inv0 = 1.f / lt0, inv1 = 1.f / lt1;

    const int r0 = q0 + wm + (lane >> 2);
    const int cq = (lane & 3) * 2;
    float* o_b = Out + ((size_t)b * SEQ) * (NQ * HD) + h * HD;
#pragma unroll
    for (int j = 0; j < 16; j++) {
        int col = j * 8 + cq;
        *(float2*)&o_b[(size_t)r0 * (NQ * HD) + col] =
            make_float2(O[j][0] * inv0, O[j][1] * inv0);
        *(float2*)&o_b[(size_t)(r0 + 8) * (NQ * HD) + col] =
            make_float2(O[j][2] * inv1, O[j][3] * inv1);
    }
}

// ---------------- launcher ----------------------------------------------------
static inline void quantize(const float* src, __half* dst, size_t n)
{
    int n4 = (int)(n / 4);
    quant_kernel<<<(n4 + 255) / 256, 256>>>(src, dst, n4);
}

extern "C" void kernel_launch(void* const* d_in, const int* in_sizes, int n_in,
                              void* d_out, int out_size)
{
    const float* X    = (const float*)d_in[0];
    const float* mask = (const float*)d_in[1];
    const void*  pos  = (const void*)d_in[2];
    const float* wq   = (const float*)d_in[3];
    const float* bq   = (const float*)d_in[4];
    const float* wk   = (const float*)d_in[5];
    const float* bk   = (const float*)d_in[6];
    const float* wv   = (const float*)d_in[7];
    const float* bv   = (const float*)d_in[8];
    const float* wo   = (const float*)d_in[9];
    float*       out  = (float*)d_out;

    float* tmp;
    __half *a, *wgt, *q, *k, *v;
    cudaGetSymbolAddress((void**)&tmp, g_tmp);
    cudaGetSymbolAddress((void**)&a,   g_a);
    cudaGetSymbolAddress((void**)&wgt, g_w);
    cudaGetSymbolAddress((void**)&q,   g_q);
    cudaGetSymbolAddress((void**)&k,   g_k);
    cudaGetSymbolAddress((void**)&v,   g_v);

    cudaFuncSetAttribute(attn_mma, cudaFuncAttributeMaxDynamicSharedMemorySize,
                         SM_TOTAL);

    const int M = BATCH * SEQ;   // 4096

    quantize(X, a, (size_t)M * HIDDEN);

    // Q projection + RoPE (scaled)
    {
        quantize(wq, wgt, (size_t)(NQ * HD) * HIDDEN);
        dim3 grid((NQ * HD) / 128, M / 128);
        gemm_fp16<<<grid, 256>>>(a, wgt, bq, tmp, M, NQ * HD, HIDDEN);
        int total = BATCH * NQ * SEQ * 64;
        rope_half<<<(total + 255) / 256, 256>>>(tmp, q, pos, NQ, QSCALE, total);
    }
    // K projection + RoPE
    {
        quantize(wk, wgt, (size_t)(NKV * HD) * HIDDEN);
        dim3 grid((NKV * HD) / 128, M / 128);
        gemm_fp16<<<grid, 256>>>(a, wgt, bk, tmp, M, NKV * HD, HIDDEN);
        int total = BATCH * NKV * SEQ * 64;
        rope_half<<<(total + 255) / 256, 256>>>(tmp, k, pos, NKV, 1.0f, total);
    }
    // V projection + transpose
    {
        quantize(wv, wgt, (size_t)(NKV * HD) * HIDDEN);
        dim3 grid((NKV * HD) / 128, M / 128);
        gemm_fp16<<<grid, 256>>>(a, wgt, bv, tmp, M, NKV * HD, HIDDEN);
        int total = BATCH * NKV * HD * SEQ;
        vtrans_half<<<(total + 255) / 256, 256>>>(tmp, v, total);
    }
    // attention -> context in [B,S,Hq*D]
    {
        dim3 grid(SEQ / AQW, NQ, BATCH);
        attn_mma<<<grid, 128, SM_TOTAL>>>(q, k, v, mask, tmp);
    }
    // output projection (no bias)
    {
        quantize(tmp, a, (size_t)M * HIDDEN);
        quantize(wo, wgt, (size_t)HIDDEN * HIDDEN);
        dim3 grid(HIDDEN / 128, M / 128);
        gemm_fp16<<<grid, 256>>>(a, wgt, nullptr, out, M, HIDDEN, HIDDEN);
    }
}

// round 9
// speedup vs baseline: 31.2623x; 1.0080x over previous
#include <cuda_runtime.h>
#include <cuda_bf16.h>
#include <cuda_fp16.h>
#include <math.h>
#include <stdint.h>

#define HIDDEN 3584
#define NQ 28
#define NKV 4
#define HD 128
#define SEQ 2048
#define BATCH 2
#define NREP (NQ / NKV)
#define QSCALE 0.08838834764831845f   // 1/sqrt(128)

// ---------------- scratch (static device arrays; no cudaMalloc) -------------
__device__ float  g_tmp[BATCH * SEQ * HIDDEN];         // proj GEMM out (fp32)
__device__ __half g_a[BATCH * SEQ * HIDDEN];           // GEMM A: X quant, later ctx
__device__ __half g_wq[NQ * HD * HIDDEN];
__device__ __half g_wk[NKV * HD * HIDDEN];
__device__ __half g_wv[NKV * HD * HIDDEN];
__device__ __half g_wo[HIDDEN * HIDDEN];
__device__ __half g_q[BATCH * NQ * SEQ * HD];          // Q [B,Hq,S,D] (pre-scaled)
__device__ __half g_k[BATCH * NKV * SEQ * HD];         // K [B,Hkv,S,D]
__device__ __half g_v[BATCH * NKV * HD * SEQ];         // V [B,Hkv,D,S] (transposed)
__device__ float  g_cs[SEQ * 64];                      // RoPE cos table
__device__ float  g_sn[SEQ * 64];                      // RoPE sin table

// ---------------- fp32 -> fp16 quantizers ------------------------------------
__device__ __forceinline__ void q4(const float* src, __half* dst, int j)
{
    float4 v = ((const float4*)src)[j];
    __half2* op = (__half2*)(dst + 4 * (size_t)j);
    op[0] = __floats2half2_rn(v.x, v.y);
    op[1] = __floats2half2_rn(v.z, v.w);
}

__global__ void quant_kernel(const float* __restrict__ in,
                             __half* __restrict__ out, int n4)
{
    int i = blockIdx.x * blockDim.x + threadIdx.x;
    if (i >= n4) return;
    q4(in, out, i);
}

// merged 4-segment weight quantizer (sizes in float4 units)
__global__ void quant4_kernel(const float* a, const float* b,
                              const float* c, const float* d,
                              __half* oa, __half* ob, __half* oc, __half* od,
                              int na, int nb, int nc, int nd)
{
    int i = blockIdx.x * blockDim.x + threadIdx.x;
    int j = i;
    if (j < na) { q4(a, oa, j); return; }
    j -= na;
    if (j < nb) { q4(b, ob, j); return; }
    j -= nb;
    if (j < nc) { q4(c, oc, j); return; }
    j -= nc;
    if (j < nd) { q4(d, od, j); return; }
}

// ---------------- mma / cp.async helpers ------------------------------------
__device__ __forceinline__ void ldsm4(uint32_t* r, uint32_t saddr)
{
    asm volatile("ldmatrix.sync.aligned.m8n8.x4.shared.b16 {%0,%1,%2,%3}, [%4];"
                 : "=r"(r[0]), "=r"(r[1]), "=r"(r[2]), "=r"(r[3]) : "r"(saddr));
}
__device__ __forceinline__ void mma_fp16(float* c, const uint32_t* a,
                                         uint32_t b0, uint32_t b1)
{
    asm volatile(
        "mma.sync.aligned.m16n8k16.row.col.f32.f16.f16.f32 "
        "{%0,%1,%2,%3}, {%4,%5,%6,%7}, {%8,%9}, {%0,%1,%2,%3};"
        : "+f"(c[0]), "+f"(c[1]), "+f"(c[2]), "+f"(c[3])
        : "r"(a[0]), "r"(a[1]), "r"(a[2]), "r"(a[3]), "r"(b0), "r"(b1));
}
__device__ __forceinline__ void cp16(uint32_t dst, const void* src)
{
    asm volatile("cp.async.ca.shared.global [%0], [%1], 16;" :: "r"(dst), "l"(src));
}
#define CP_COMMIT() asm volatile("cp.async.commit_group;")
#define CP_WAIT0()  asm volatile("cp.async.wait_group 0;")
#define CP_WAIT1()  asm volatile("cp.async.wait_group 1;")

__device__ __forceinline__ float qmax4(float v)
{
    v = fmaxf(v, __shfl_xor_sync(0xffffffffu, v, 1));
    v = fmaxf(v, __shfl_xor_sync(0xffffffffu, v, 2));
    return v;
}
__device__ __forceinline__ float qsum4(float v)
{
    v += __shfl_xor_sync(0xffffffffu, v, 1);
    v += __shfl_xor_sync(0xffffffffu, v, 2);
    return v;
}

// ---------------- fp16 tensor GEMM (3-stage): C = A*W^T (+bias) -------------
// A: [M,K] fp16, W: [N,K] fp16. M,N %128==0, K%32==0.
#define SA 40
#define GSTAGE_B (128 * SA * 2)          // 10240 bytes per operand per stage
#define GSM_TOTAL (6 * GSTAGE_B)         // 61440

__global__ __launch_bounds__(256) void gemm_fp16(
    const __half* __restrict__ A, const __half* __restrict__ W,
    const float* __restrict__ bias, float* __restrict__ C,
    int M, int N, int K)
{
    extern __shared__ __align__(16) char gsm[];
    const uint32_t smAb = (uint32_t)__cvta_generic_to_shared(gsm);
    const uint32_t smWb = smAb + 3 * GSTAGE_B;

    const int t    = threadIdx.x;
    const int lane = t & 31;
    const int wid  = t >> 5;
    const int wm   = (wid >> 2) * 64;
    const int wn   = (wid & 3) * 32;
    const int m0   = blockIdx.y * 128;
    const int n0   = blockIdx.x * 128;

    const int r1 = t >> 2;
    const int r2 = r1 + 64;
    const int c1 = (t & 3) * 8;

    const int nk = K / 32;

    float acc[4][4][4];
#pragma unroll
    for (int i = 0; i < 4; i++)
#pragma unroll
        for (int j = 0; j < 4; j++)
#pragma unroll
            for (int e = 0; e < 4; e++) acc[i][j][e] = 0.f;

    auto issue = [&](int tile, int st) {
        int kk = tile * 32;
        uint32_t dA = smAb + st * GSTAGE_B;
        uint32_t dW = smWb + st * GSTAGE_B;
        cp16(dA + (r1 * SA + c1) * 2, A + (size_t)(m0 + r1) * K + kk + c1);
        cp16(dA + (r2 * SA + c1) * 2, A + (size_t)(m0 + r2) * K + kk + c1);
        cp16(dW + (r1 * SA + c1) * 2, W + (size_t)(n0 + r1) * K + kk + c1);
        cp16(dW + (r2 * SA + c1) * 2, W + (size_t)(n0 + r2) * K + kk + c1);
        CP_COMMIT();
    };

    issue(0, 0);
    issue(1, 1);

    for (int p = 0; p < nk; p++) {
        if (p + 1 < nk) { CP_WAIT1(); } else { CP_WAIT0(); }
        __syncthreads();
        if (p + 2 < nk) issue(p + 2, (p + 2) % 3);

        const int cur = p % 3;
        const uint32_t bA = smAb + cur * GSTAGE_B;
        const uint32_t bW = smWb + cur * GSTAGE_B;
#pragma unroll
        for (int kk = 0; kk < 32; kk += 16) {
            const int arow = (lane & 15);
            const int acol = kk + (lane >> 4) * 8;
            uint32_t a[4][4], bfr[2][4];
#pragma unroll
            for (int mi = 0; mi < 4; mi++)
                ldsm4(a[mi], bA + ((wm + mi * 16 + arow) * SA + acol) * 2);
#pragma unroll
            for (int bi = 0; bi < 2; bi++)
                ldsm4(bfr[bi], bW + ((wn + bi * 16 + arow) * SA + acol) * 2);
#pragma unroll
            for (int mi = 0; mi < 4; mi++)
#pragma unroll
                for (int bi = 0; bi < 2; bi++)
#pragma unroll
                    for (int h = 0; h < 2; h++)
                        mma_fp16(acc[mi][bi * 2 + h], a[mi],
                                 bfr[bi][h], bfr[bi][2 + h]);
        }
    }

#pragma unroll
    for (int mi = 0; mi < 4; mi++) {
        int row0 = m0 + wm + mi * 16 + (lane >> 2);
#pragma unroll
        for (int nj = 0; nj < 4; nj++) {
            int col0 = n0 + wn + nj * 8 + (lane & 3) * 2;
            float b0 = bias ? bias[col0] : 0.f;
            float b1 = bias ? bias[col0 + 1] : 0.f;
            float* c = acc[mi][nj];
            float2 v0 = make_float2(c[0] + b0, c[1] + b1);
            float2 v1 = make_float2(c[2] + b0, c[3] + b1);
            *(float2*)&C[(size_t)row0 * N + col0]       = v0;
            *(float2*)&C[(size_t)(row0 + 8) * N + col0] = v1;
        }
    }
}

// ---------------- robust position decode (int64 / int32 / float32) ----------
__device__ __forceinline__ float get_pos(const void* pos, int s)
{
    const int* p32 = (const int*)pos;
    if (p32[2] == 1 && p32[3] == 0) {
        return (float)((const long long*)pos)[s];
    } else if (p32[1] == 1 && p32[2] == 2) {
        return (float)p32[s];
    } else {
        return ((const float*)pos)[s];
    }
}

// ---------------- RoPE table (once): cos/sin[S][64] --------------------------
__global__ void rope_table(const void* __restrict__ pos)
{
    int idx = blockIdx.x * blockDim.x + threadIdx.x;
    if (idx >= SEQ * 64) return;
    int d = idx & 63, s = idx >> 6;
    float inv = powf(1000000.0f, -(float)d / 64.0f);
    float ang = get_pos(pos, s) * inv;
    float sn, cs;
    sincosf(ang, &sn, &cs);
    g_cs[idx] = cs;
    g_sn[idx] = sn;
}

// ------- RoPE + transpose + scale -> fp16:  [B,S,H,D] -> [B,H,S,D] ----------
__global__ void rope_half(const float* __restrict__ in, __half* __restrict__ out,
                          int H, float scale, int total)
{
    int idx = blockIdx.x * blockDim.x + threadIdx.x;
    if (idx >= total) return;          // total = B*H*S*64
    int per = idx;
    int d = per & 63;     per >>= 6;
    int s = per & (SEQ - 1); per /= SEQ;
    int h = per % H;
    int b = per / H;

    size_t ibase = (((size_t)b * SEQ + s) * H + h) * HD;
    float x1 = in[ibase + d];
    float x2 = in[ibase + d + 64];

    float cs = g_cs[(s << 6) + d];
    float sn = g_sn[(s << 6) + d];

    size_t obase = (((size_t)b * H + h) * SEQ + s) * HD;
    out[obase + d]      = __float2half((x1 * cs - x2 * sn) * scale);
    out[obase + d + 64] = __float2half((x2 * cs + x1 * sn) * scale);
}

// ---- V transpose -> fp16: [B,S,Hkv,D] -> [B,Hkv,D,S] -----------------------
__global__ void vtrans_half(const float* __restrict__ in, __half* __restrict__ out,
                            int total)
{
    int idx = blockIdx.x * blockDim.x + threadIdx.x;
    if (idx >= total) return;          // total = B*NKV*HD*SEQ
    int per = idx;
    int s = per & (SEQ - 1); per >>= 11;
    int d = per & (HD - 1);  per >>= 7;
    int h = per % NKV;
    int b = per / NKV;
    out[idx] = __float2half(in[(((size_t)b * SEQ + s) * NKV + h) * HD + d]);
}

// ---------------- mma flash attention (fp16, 2-stage K/V) --------------------
// CTA: 64 q-rows, 4 warps (m16 each); tiles of 64 keys; D=128.
#define AQW 64
#define KTS 64
#define KSTR 136    // K/Q smem row stride (fp16)
#define VSTR 72     // Vt smem row stride (fp16)
#define ASTAGE_B (KTS * KSTR * 2 + HD * VSTR * 2)   // 35840 per stage
#define ASM_TOTAL (2 * ASTAGE_B)                    // 71680

__global__ __launch_bounds__(128) void attn_mma(
    const __half* __restrict__ Qg, const __half* __restrict__ Kg,
    const __half* __restrict__ Vg, const float* __restrict__ maskg,
    __half* __restrict__ Out)
{
    extern __shared__ __align__(16) char smraw[];
    const uint32_t smb = (uint32_t)__cvta_generic_to_shared(smraw);

    const int t    = threadIdx.x;
    const int lane = t & 31;
    const int w    = t >> 5;
    const int q0   = blockIdx.x * AQW;
    const int h    = blockIdx.y;
    const int b    = blockIdx.z;
    const int hkv  = h / NREP;
    const int wm   = w * 16;

    const __half* q_b = Qg + (((size_t)(b * NQ + h) * SEQ) + q0) * HD;
    const __half* k_b = Kg + (size_t)(b * NKV + hkv) * SEQ * HD;
    const __half* v_b = Vg + (size_t)(b * NKV + hkv) * HD * SEQ;
    const float*  m_b = maskg + ((size_t)b * SEQ + q0) * SEQ;

    // ---- stage Q tile in stage-0 K area, load fragments ----
    for (int c = t; c < 1024; c += 128) {
        int row = c >> 4, off = (c & 15) * 8;
        cp16(smb + (row * KSTR + off) * 2, q_b + (size_t)row * HD + off);
    }
    CP_COMMIT(); CP_WAIT0();
    __syncthreads();

    uint32_t qf[8][4];
    {
        const int arow = lane & 15;
#pragma unroll
        for (int ks = 0; ks < 8; ks++) {
            int acol = ks * 16 + (lane >> 4) * 8;
            ldsm4(qf[ks], smb + ((wm + arow) * KSTR + acol) * 2);
        }
    }
    __syncthreads();

    auto loadKV = [&](int kt, int buf) {
        int k0 = kt * KTS;
        uint32_t smk = smb + buf * ASTAGE_B;
        uint32_t smv = smk + KTS * KSTR * 2;
        for (int c = t; c < 1024; c += 128) {
            int row = c >> 4, off = (c & 15) * 8;
            cp16(smk + (row * KSTR + off) * 2, k_b + (size_t)(k0 + row) * HD + off);
        }
        for (int c = t; c < 1024; c += 128) {
            int row = c >> 3, off = (c & 7) * 8;
            cp16(smv + (row * VSTR + off) * 2, v_b + (size_t)row * SEQ + k0 + off);
        }
        CP_COMMIT();
    };

    float O[16][4];
#pragma unroll
    for (int j = 0; j < 16; j++)
#pragma unroll
        for (int e = 0; e < 4; e++) O[j][e] = 0.f;
    float mrow0 = -1e30f, mrow1 = -1e30f;
    float lrow0 = 0.f, lrow1 = 0.f;

    const int r0q = wm + (lane >> 2);   // row within q-tile
    const int cq  = (lane & 3) * 2;
    const float* mrow_a = m_b + (size_t)r0q * SEQ;
    const float* mrow_b = m_b + (size_t)(r0q + 8) * SEQ;

    loadKV(0, 0);

    const int NT = SEQ / KTS;
    for (int kt = 0; kt < NT; kt++) {
        const int cur = kt & 1;
        CP_WAIT0();
        __syncthreads();
        if (kt + 1 < NT) loadKV(kt + 1, cur ^ 1);

        const uint32_t smk = smb + cur * ASTAGE_B;
        const uint32_t smv = smk + KTS * KSTR * 2;
        const int k0 = kt * KTS;

        // ---- scores: S = Q*K^T  (m16 x n64, k=128) ----
        float sc[8][4];
#pragma unroll
        for (int j = 0; j < 8; j++)
#pragma unroll
            for (int e = 0; e < 4; e++) sc[j][e] = 0.f;

        const int arow = lane & 15;
#pragma unroll
        for (int ks = 0; ks < 8; ks++) {
            int acol = ks * 16 + (lane >> 4) * 8;
#pragma unroll
            for (int n = 0; n < 4; n++) {
                uint32_t bk[4];
                ldsm4(bk, smk + ((n * 16 + arow) * KSTR + acol) * 2);
#pragma unroll
                for (int hh = 0; hh < 2; hh++)
                    mma_fp16(sc[n * 2 + hh], qf[ks], bk[hh], bk[2 + hh]);
            }
        }

        // ---- + mask (direct from L2), online softmax ----
        float mx0 = -1e30f, mx1 = -1e30f;
#pragma unroll
        for (int j = 0; j < 8; j++) {
            float2 mk0 = __ldg((const float2*)(mrow_a + k0 + j * 8 + cq));
            float2 mk1 = __ldg((const float2*)(mrow_b + k0 + j * 8 + cq));
            sc[j][0] += mk0.x; sc[j][1] += mk0.y;
            sc[j][2] += mk1.x; sc[j][3] += mk1.y;
            mx0 = fmaxf(mx0, fmaxf(sc[j][0], sc[j][1]));
            mx1 = fmaxf(mx1, fmaxf(sc[j][2], sc[j][3]));
        }
        mx0 = qmax4(mx0); mx1 = qmax4(mx1);
        float mn0 = fmaxf(mrow0, mx0), mn1 = fmaxf(mrow1, mx1);
        float cr0 = __expf(mrow0 - mn0), cr1 = __expf(mrow1 - mn1);
        mrow0 = mn0; mrow1 = mn1;
        lrow0 *= cr0; lrow1 *= cr1;
#pragma unroll
        for (int j = 0; j < 16; j++) {
            O[j][0] *= cr0; O[j][1] *= cr0;
            O[j][2] *= cr1; O[j][3] *= cr1;
        }

        uint32_t ap[4][4];
#pragma unroll
        for (int j = 0; j < 8; j++) {
            float p0 = __expf(sc[j][0] - mn0);
            float p1 = __expf(sc[j][1] - mn0);
            float p2 = __expf(sc[j][2] - mn1);
            float p3 = __expf(sc[j][3] - mn1);
            lrow0 += p0 + p1; lrow1 += p2 + p3;
            int kk = j >> 1, hi = j & 1;
            __half2 ph01 = __floats2half2_rn(p0, p1);
            __half2 ph23 = __floats2half2_rn(p2, p3);
            ap[kk][hi * 2 + 0] = *(uint32_t*)&ph01;
            ap[kk][hi * 2 + 1] = *(uint32_t*)&ph23;
        }

        // ---- PV: O += P*V^T  (m16 x n128, k=64 keys) ----
#pragma unroll
        for (int kk = 0; kk < 4; kk++) {
            int acol = kk * 16 + (lane >> 4) * 8;
#pragma unroll
            for (int n = 0; n < 8; n++) {
                uint32_t bv[4];
                ldsm4(bv, smv + ((n * 16 + arow) * VSTR + acol) * 2);
#pragma unroll
                for (int hh = 0; hh < 2; hh++)
                    mma_fp16(O[n * 2 + hh], ap[kk], bv[hh], bv[2 + hh]);
            }
        }
    }

    // ---- finalize: O /= l, write fp16 context [B,S,NQ*D] ----
    float lt0 = qsum4(lrow0), lt1 = qsum4(lrow1);
    float inv0 = 1.f / lt0, inv1 = 1.f / lt1;

    const int r0 = q0 + r0q;
    __half* o_b = Out + ((size_t)b * SEQ) * (NQ * HD) + h * HD;
#pragma unroll
    for (int j = 0; j < 16; j++) {
        int col = j * 8 + cq;
        __half2 v0 = __floats2half2_rn(O[j][0] * inv0, O[j][1] * inv0);
        __half2 v1 = __floats2half2_rn(O[j][2] * inv1, O[j][3] * inv1);
        *(__half2*)&o_b[(size_t)r0 * (NQ * HD) + col]       = v0;
        *(__half2*)&o_b[(size_t)(r0 + 8) * (NQ * HD) + col] = v1;
    }
}

// ---------------- launcher ----------------------------------------------------
extern "C" void kernel_launch(void* const* d_in, const int* in_sizes, int n_in,
                              void* d_out, int out_size)
{
    const float* X    = (const float*)d_in[0];
    const float* mask = (const float*)d_in[1];
    const void*  pos  = (const void*)d_in[2];
    const float* wq   = (const float*)d_in[3];
    const float* bq   = (const float*)d_in[4];
    const float* wk   = (const float*)d_in[5];
    const float* bk   = (const float*)d_in[6];
    const float* wv   = (const float*)d_in[7];
    const float* bv   = (const float*)d_in[8];
    const float* wo   = (const float*)d_in[9];
    float*       out  = (float*)d_out;

    float* tmp;
    __half *a, *pwq, *pwk, *pwv, *pwo, *q, *k, *v;
    cudaGetSymbolAddress((void**)&tmp, g_tmp);
    cudaGetSymbolAddress((void**)&a,   g_a);
    cudaGetSymbolAddress((void**)&pwq, g_wq);
    cudaGetSymbolAddress((void**)&pwk, g_wk);
    cudaGetSymbolAddress((void**)&pwv, g_wv);
    cudaGetSymbolAddress((void**)&pwo, g_wo);
    cudaGetSymbolAddress((void**)&q,   g_q);
    cudaGetSymbolAddress((void**)&k,   g_k);
    cudaGetSymbolAddress((void**)&v,   g_v);

    cudaFuncSetAttribute(attn_mma, cudaFuncAttributeMaxDynamicSharedMemorySize,
                         ASM_TOTAL);
    cudaFuncSetAttribute(gemm_fp16, cudaFuncAttributeMaxDynamicSharedMemorySize,
                         GSM_TOTAL);

    const int M = BATCH * SEQ;   // 4096

    // all weight quants in one launch
    {
        const int nq4 = (NQ * HD * HIDDEN) / 4;      // 3,211,264
        const int nk4 = (NKV * HD * HIDDEN) / 4;     //   458,752
        const int no4 = (HIDDEN * HIDDEN) / 4;       // 3,211,264
        int total = nq4 + 2 * nk4 + no4;
        quant4_kernel<<<(total + 255) / 256, 256>>>(wq, wk, wv, wo,
                                                    pwq, pwk, pwv, pwo,
                                                    nq4, nk4, nk4, no4);
    }
    // X quant + RoPE table
    {
        int n4 = (M * HIDDEN) / 4;
        quant_kernel<<<(n4 + 255) / 256, 256>>>(X, a, n4);
        rope_table<<<(SEQ * 64 + 255) / 256, 256>>>(pos);
    }

    // Q projection + RoPE (scaled)
    {
        dim3 grid((NQ * HD) / 128, M / 128);
        gemm_fp16<<<grid, 256, GSM_TOTAL>>>(a, pwq, bq, tmp, M, NQ * HD, HIDDEN);
        int total = BATCH * NQ * SEQ * 64;
        rope_half<<<(total + 255) / 256, 256>>>(tmp, q, NQ, QSCALE, total);
    }
    // K projection + RoPE
    {
        dim3 grid((NKV * HD) / 128, M / 128);
        gemm_fp16<<<grid, 256, GSM_TOTAL>>>(a, pwk, bk, tmp, M, NKV * HD, HIDDEN);
        int total = BATCH * NKV * SEQ * 64;
        rope_half<<<(total + 255) / 256, 256>>>(tmp, k, NKV, 1.0f, total);
    }
    // V projection + transpose
    {
        dim3 grid((NKV * HD) / 128, M / 128);
        gemm_fp16<<<grid, 256, GSM_TOTAL>>>(a, pwv, bv, tmp, M, NKV * HD, HIDDEN);
        int total = BATCH * NKV * HD * SEQ;
        vtrans_half<<<(total + 255) / 256, 256>>>(tmp, v, total);
    }
    // attention -> fp16 context written into g_a (X no longer needed)
    {
        dim3 grid(SEQ / AQW, NQ, BATCH);
        attn_mma<<<grid, 128, ASM_TOTAL>>>(q, k, v, mask, a);
    }
    // output projection (no bias)
    {
        dim3 grid(HIDDEN / 128, M / 128);
        gemm_fp16<<<grid, 256, GSM_TOTAL>>>(a, pwo, nullptr, out, M, HIDDEN, HIDDEN);
    }
}